// round 14
// baseline (speedup 1.0000x reference)
#include <cuda_runtime.h>
#include <cuda_bf16.h>
#include <math.h>
#include <stdint.h>

// ---------------- problem constants ----------------
#define B_   4
#define S_   4096
#define D_   1024
#define H_   16
#define DH_  64
#define P_   16
#define C_   512
#define FF_  4096
#define NTOK 2048      /* B_*C_ tokens per chunk */
#define PC_  528       /* P_ + C_ */
#define PCs  640       /* padded score stride */
#define NCH  8         /* S_/C_ chunks */

// ---------------- device scratch (no allocation allowed) ----------------
__device__ float g_M   [(size_t)B_*D_*D_];      // TRANSPOSED: Mt[v][k] = M[k][v]
__device__ float g_St  [(size_t)B_*D_*D_];
__device__ float g_grad[(size_t)B_*D_*D_];
__device__ float g_h1  [(size_t)NTOK*D_];
__device__ float g_mm3 [(size_t)NTOK*3072];     // [qm|km|vm] ld=3072
__device__ float g_mp  [(size_t)2*NTOK*D_];     // [mem_ctx ; pred] contiguous
__device__ float g_h2  [(size_t)NTOK*D_];
__device__ float g_qkv [(size_t)NTOK*3072];     // [qh|kh|vh] ld=3072
__device__ float g_kf  [(size_t)B_*PC_*D_];
__device__ float g_vf  [(size_t)B_*PC_*D_];
__device__ float g_sc  [(size_t)B_*H_*C_*PCs];
__device__ float g_ao  [(size_t)NTOK*D_];
__device__ float g_ap  [(size_t)NTOK*D_];
__device__ float g_gt  [(size_t)NTOK*D_];
__device__ float g_h3  [(size_t)NTOK*D_];
__device__ float g_ff  [(size_t)NTOK*8192];     // [gate|up] ld=8192
__device__ float g_bias3 [3072];
__device__ float g_biasff[8192];
// pre-transposed weights [N,K] in tf32 (u32), k pair-permuted per 32-chunk
#define WTOT 20971520
__device__ uint32_t g_wt[WTOT];

__device__ __forceinline__ void cvt2(float x, __nv_bfloat16& h, __nv_bfloat16& l) {
    h = __float2bfloat16(x);
    l = __float2bfloat16(x - __bfloat162float(h));
}
__device__ __forceinline__ uint32_t f2tf(float x) {
    uint32_t r; asm("cvt.rna.tf32.f32 %0, %1;" : "=r"(r) : "f"(x)); return r;
}

// =====================================================================
//   weight transpose+tf32:  src[K,N] fp32 -> dst[N,K] tf32,
//   k pair-permuted within 32-word chunks
// =====================================================================
__global__ void wtf32_k(const float* __restrict__ src, uint32_t* __restrict__ dst,
                        int K, int N)
{
    __shared__ float t[32][33];
    int nb = blockIdx.x * 32, kb = blockIdx.y * 32;
    int tx = threadIdx.x, ty = threadIdx.y;
#pragma unroll
    for (int i = 0; i < 32; i += 8)
        t[ty + i][tx] = src[(long long)(kb + ty + i) * N + nb + tx];
    __syncthreads();
    int ks = tx >> 3, rem = tx & 7;
    int s_local = (rem & 3) * 8 + ks * 2 + (rem >> 2);
#pragma unroll
    for (int i = 0; i < 32; i += 8) {
        long long o = (long long)(nb + ty + i) * K + kb + s_local;
        dst[o] = f2tf(t[tx][ty + i]);
    }
}

__global__ void cat3_k(const float* a, const float* b, const float* c, float* d) {
    int i = blockIdx.x * 256 + threadIdx.x;
    d[i] = (i < 1024) ? a[i] : (i < 2048) ? b[i - 1024] : c[i - 2048];
}
__global__ void cat2_k(const float* a, const float* b, float* d) {
    int i = blockIdx.x * 256 + threadIdx.x;
    d[i] = (i < 4096) ? a[i] : b[i - 4096];
}

// =====================================================================
//      bf16 split GEMM (state GEMMs): block 128x128x32, 8 warps
// =====================================================================
#define TILE_B 10240              /* 128 rows x 80 bytes */
#define SMEM_MM (8*TILE_B)        /* 81920 */

#define MMA_B16(c, a0, a1, a2, a3, b0, b1)                                     \
    asm volatile("mma.sync.aligned.m16n8k16.row.col.f32.bf16.bf16.f32 "        \
                 "{%0,%1,%2,%3}, {%4,%5,%6,%7}, {%8,%9}, {%0,%1,%2,%3};"       \
                 : "+f"(c[0]), "+f"(c[1]), "+f"(c[2]), "+f"(c[3])              \
                 : "r"(a0), "r"(a1), "r"(a2), "r"(a3), "r"(b0), "r"(b1))

#define MMA_TF32(c, a0, a1, a2, a3, b0, b1)                                    \
    asm volatile("mma.sync.aligned.m16n8k8.row.col.f32.tf32.tf32.f32 "         \
                 "{%0,%1,%2,%3}, {%4,%5,%6,%7}, {%8,%9}, {%0,%1,%2,%3};"       \
                 : "+f"(c[0]), "+f"(c[1]), "+f"(c[2]), "+f"(c[3])              \
                 : "r"(a0), "r"(a1), "r"(a2), "r"(a3), "r"(b0), "r"(b1))

// ---- fp32 loaders (bf16 hi/lo commit) ----
template<int TR>
__device__ __forceinline__ void issue_f32(const float* __restrict__ src, long long ld,
                                          int row0, int k0, int tid, float4 v[4]) {
    if (TR == 0) {
        int r = tid >> 1, h = tid & 1;
#pragma unroll
        for (int i = 0; i < 4; i++)
            v[i] = *(const float4*)(src + (long long)(row0 + r) * ld + k0 + h * 16 + i * 4);
    } else {
        int kk = tid >> 3, q = tid & 7;
#pragma unroll
        for (int i = 0; i < 4; i++)
            v[i] = *(const float4*)(src + (long long)(k0 + kk) * ld + row0 + (q + i * 8) * 4);
    }
}
template<int TR>
__device__ __forceinline__ void commit_f32(char* dhi, char* dlo, int tid, const float4 v[4]) {
    if (TR == 0) {
        int r = tid >> 1, h = tid & 1;
#pragma unroll
        for (int i = 0; i < 4; i++) {
            int c = h * 16 + i * 4;
            __nv_bfloat16 h0, h1, h2, h3, l0, l1, l2, l3;
            cvt2(v[i].x, h0, l0); cvt2(v[i].y, h1, l1);
            cvt2(v[i].z, h2, l2); cvt2(v[i].w, h3, l3);
            uint2 hp, lp;
            hp.x = (uint32_t)__bfloat16_as_ushort(h0) | ((uint32_t)__bfloat16_as_ushort(h1) << 16);
            hp.y = (uint32_t)__bfloat16_as_ushort(h2) | ((uint32_t)__bfloat16_as_ushort(h3) << 16);
            lp.x = (uint32_t)__bfloat16_as_ushort(l0) | ((uint32_t)__bfloat16_as_ushort(l1) << 16);
            lp.y = (uint32_t)__bfloat16_as_ushort(l2) | ((uint32_t)__bfloat16_as_ushort(l3) << 16);
            *(uint2*)(dhi + r * 80 + c * 2) = hp;
            *(uint2*)(dlo + r * 80 + c * 2) = lp;
        }
    } else {
        int kk = tid >> 3, q = tid & 7;
#pragma unroll
        for (int i = 0; i < 4; i++) {
            int m = (q + i * 8) * 4;
            float xs[4] = {v[i].x, v[i].y, v[i].z, v[i].w};
#pragma unroll
            for (int j = 0; j < 4; j++) {
                __nv_bfloat16 h, l;
                cvt2(xs[j], h, l);
                *(__nv_bfloat16*)(dhi + (m + j) * 80 + kk * 2) = h;
                *(__nv_bfloat16*)(dlo + (m + j) * 80 + kk * 2) = l;
            }
        }
    }
}

template<int TRA, int TRB, int EPI>
__global__ void __launch_bounds__(256, 1) mm_k(
    const float* __restrict__ A, const float* __restrict__ Bf,
    const float* __restrict__ bias, float* __restrict__ Cm,
    int M, int N, int K, long long lda, long long ldb, long long ldc, float scale,
    int zdiv,
    long long aO, long long aI, long long bO, long long bI, long long cO, long long cI)
{
    extern __shared__ char smem[];
    int z = blockIdx.z;
    int zq = z / zdiv, zr = z % zdiv;
    A  += zq * aO + zr * aI;
    Bf += zq * bO + zr * bI;
    Cm += zq * cO + zr * cI;

    int tid = threadIdx.x, wid = tid >> 5, lid = tid & 31;
    int m0 = blockIdx.y * 128, n0 = blockIdx.x * 128;

    float acc[2][8][4];
#pragma unroll
    for (int mi = 0; mi < 2; mi++)
#pragma unroll
        for (int ni = 0; ni < 8; ni++)
#pragma unroll
            for (int j = 0; j < 4; j++) acc[mi][ni][j] = 0.f;

    {
        float4 va[4], vb[4];
        issue_f32<TRA>(A, lda, m0, 0, tid, va);
        commit_f32<TRA>(smem, smem + TILE_B, tid, va);
        issue_f32<TRB>(Bf, ldb, n0, 0, tid, vb);
        commit_f32<TRB>(smem + 2 * TILE_B, smem + 3 * TILE_B, tid, vb);
    }
    __syncthreads();

    int g = lid >> 2, t4 = lid & 3;
    int mbase = (wid & 3) * 32, nbase = (wid >> 2) * 64;
    int KT = K / 32;

    for (int kt = 0; kt < KT; kt++) {
        char* cur = smem + (kt & 1) * 4 * TILE_B;
        char* nxt = smem + ((kt + 1) & 1) * 4 * TILE_B;
        float4 va[4], vb[4];
        bool more = (kt + 1 < KT);
        if (more) {
            issue_f32<TRA>(A, lda, m0, (kt + 1) * 32, tid, va);
            issue_f32<TRB>(Bf, ldb, n0, (kt + 1) * 32, tid, vb);
        }
        char* Ah = cur;              char* Al = cur + TILE_B;
        char* Bh = cur + 2 * TILE_B; char* Bl = cur + 3 * TILE_B;
#pragma unroll
        for (int k16 = 0; k16 < 2; k16++) {
            int kc = k16 * 16;
            uint32_t ah[2][4], al[2][4];
#pragma unroll
            for (int mi = 0; mi < 2; mi++) {
                int r = mbase + mi * 16 + g;
                int c = kc + t4 * 2;
                ah[mi][0] = *(uint32_t*)(Ah + r * 80 + c * 2);
                ah[mi][1] = *(uint32_t*)(Ah + (r + 8) * 80 + c * 2);
                ah[mi][2] = *(uint32_t*)(Ah + r * 80 + (c + 8) * 2);
                ah[mi][3] = *(uint32_t*)(Ah + (r + 8) * 80 + (c + 8) * 2);
                al[mi][0] = *(uint32_t*)(Al + r * 80 + c * 2);
                al[mi][1] = *(uint32_t*)(Al + (r + 8) * 80 + c * 2);
                al[mi][2] = *(uint32_t*)(Al + r * 80 + (c + 8) * 2);
                al[mi][3] = *(uint32_t*)(Al + (r + 8) * 80 + (c + 8) * 2);
            }
#pragma unroll
            for (int ni = 0; ni < 8; ni++) {
                int r = nbase + ni * 8 + g;
                int c = kc + t4 * 2;
                uint32_t bh0 = *(uint32_t*)(Bh + r * 80 + c * 2);
                uint32_t bh1 = *(uint32_t*)(Bh + r * 80 + (c + 8) * 2);
                uint32_t bl0 = *(uint32_t*)(Bl + r * 80 + c * 2);
                uint32_t bl1 = *(uint32_t*)(Bl + r * 80 + (c + 8) * 2);
#pragma unroll
                for (int mi = 0; mi < 2; mi++) {
                    MMA_B16(acc[mi][ni], ah[mi][0], ah[mi][1], ah[mi][2], ah[mi][3], bh0, bh1);
                    MMA_B16(acc[mi][ni], ah[mi][0], ah[mi][1], ah[mi][2], ah[mi][3], bl0, bl1);
                    MMA_B16(acc[mi][ni], al[mi][0], al[mi][1], al[mi][2], al[mi][3], bh0, bh1);
                }
            }
        }
        if (more) {
            commit_f32<TRA>(nxt, nxt + TILE_B, tid, va);
            commit_f32<TRB>(nxt + 2 * TILE_B, nxt + 3 * TILE_B, tid, vb);
        }
        __syncthreads();
    }

#pragma unroll
    for (int mi = 0; mi < 2; mi++)
#pragma unroll
        for (int ni = 0; ni < 8; ni++) {
            int gm = m0 + mbase + mi * 16 + g;
            int gn = n0 + nbase + ni * 8 + t4 * 2;
            const float* c = acc[mi][ni];
#pragma unroll
            for (int hrow = 0; hrow < 2; hrow++) {
                long long ci = (long long)(gm + hrow * 8) * ldc + gn;
#pragma unroll
                for (int j = 0; j < 2; j++) {
                    float v = c[hrow * 2 + j] * scale;
                    if (EPI == 1)      v += bias[gn + j];
                    else if (EPI == 2) v = 1.f / (1.f + expf(-(v + bias[gn + j])));
                    else if (EPI == 3) v += bias[gn + j] + Cm[ci + j];
                    Cm[ci + j] = v;
                }
            }
        }
}

// =====================================================================
//      TF32 single-pass weight GEMM: block 128x128, K-stage 64, 8 warps
//      A: linear layout, stride 272B (68w ≡ 4 mod 32).
//      B: pair-permuted,  stride 264B (66w ≡ 2 mod 32).
// =====================================================================
#define TFROW_A 272
#define TFROW_B 264
#define TFTILE_A (128*TFROW_A)      /* 34816 */
#define TFTILE_B (128*TFROW_B)      /* 33792 */
#define TFSTAGE  (TFTILE_A+TFTILE_B)
#define SMEM_TF  (2*TFSTAGE)        /* 137216 */

__device__ __forceinline__ void tf_issueA(const float* __restrict__ src, long long ld,
                                          int row0, int k0, int tid, float4 v[8]) {
    int r = tid >> 1, h = tid & 1;
#pragma unroll
    for (int i = 0; i < 8; i++)
        v[i] = *(const float4*)(src + (long long)(row0 + r) * ld + k0 + h * 32 + i * 4);
}
__device__ __forceinline__ void tf_commitA(char* d, int tid, const float4 v[8]) {
    int r = tid >> 1, h = tid & 1;
#pragma unroll
    for (int i = 0; i < 8; i++) {
        uint4 u;
        u.x = f2tf(v[i].x); u.y = f2tf(v[i].y); u.z = f2tf(v[i].z); u.w = f2tf(v[i].w);
        *(uint4*)(d + r * TFROW_A + (h * 32 + i * 4) * 4) = u;
    }
}
__device__ __forceinline__ void tf_issueB(const uint32_t* __restrict__ src, long long K,
                                          int n0, int k0, int tid, uint4 v[8]) {
    int r = tid >> 1, h = tid & 1;
#pragma unroll
    for (int i = 0; i < 8; i++)
        v[i] = *(const uint4*)(src + (long long)(n0 + r) * K + k0 + h * 32 + i * 4);
}
// 8B stores only: TFROW_B=264 is 8-aligned but NOT 16-aligned for odd rows
__device__ __forceinline__ void tf_commitB(char* d, int tid, const uint4 v[8]) {
    int r = tid >> 1, h = tid & 1;
    char* base = d + r * TFROW_B + h * 128;
#pragma unroll
    for (int i = 0; i < 8; i++) {
        *(uint2*)(base + i * 16)     = make_uint2(v[i].x, v[i].y);
        *(uint2*)(base + i * 16 + 8) = make_uint2(v[i].z, v[i].w);
    }
}

template<int EPI>
__global__ void __launch_bounds__(256, 1) mmtf_k(
    const float* __restrict__ A, const uint32_t* __restrict__ W,
    const float* __restrict__ bias, float* __restrict__ Cm,
    int M, int N, int K, long long lda, long long ldc, float scale,
    long long aO, long long cO)
{
    extern __shared__ char smem[];
    int z = blockIdx.z;
    A  += (long long)z * aO;
    Cm += (long long)z * cO;

    int tid = threadIdx.x, wid = tid >> 5, lid = tid & 31;
    int m0 = blockIdx.y * 128, n0 = blockIdx.x * 128;

    float acc[2][8][4];
#pragma unroll
    for (int mi = 0; mi < 2; mi++)
#pragma unroll
        for (int ni = 0; ni < 8; ni++)
#pragma unroll
            for (int j = 0; j < 4; j++) acc[mi][ni][j] = 0.f;

    {
        float4 va[8]; uint4 vb[8];
        tf_issueA(A, lda, m0, 0, tid, va);
        tf_commitA(smem, tid, va);
        tf_issueB(W, K, n0, 0, tid, vb);
        tf_commitB(smem + TFTILE_A, tid, vb);
    }
    __syncthreads();

    int g = lid >> 2, t4 = lid & 3;
    int mbase = (wid & 3) * 32, nbase = (wid >> 2) * 64;
    int KT = K / 64;

    for (int kt = 0; kt < KT; kt++) {
        char* cur = smem + (kt & 1) * TFSTAGE;
        char* nxt = smem + ((kt + 1) & 1) * TFSTAGE;
        float4 va[8]; uint4 vb[8];
        bool more = (kt + 1 < KT);
        if (more) {
            tf_issueA(A, lda, m0, (kt + 1) * 64, tid, va);
            tf_issueB(W, K, n0, (kt + 1) * 64, tid, vb);
        }
        char* Ac = cur;
        char* Bc = cur + TFTILE_A;
#pragma unroll
        for (int ks = 0; ks < 8; ks++) {
            int kc = ks * 8;
            uint32_t a[2][4];
#pragma unroll
            for (int mi = 0; mi < 2; mi++) {
                int r = mbase + mi * 16 + g;
                a[mi][0] = *(uint32_t*)(Ac + r * TFROW_A + (kc + t4) * 4);
                a[mi][1] = *(uint32_t*)(Ac + (r + 8) * TFROW_A + (kc + t4) * 4);
                a[mi][2] = *(uint32_t*)(Ac + r * TFROW_A + (kc + t4 + 4) * 4);
                a[mi][3] = *(uint32_t*)(Ac + (r + 8) * TFROW_A + (kc + t4 + 4) * 4);
            }
            // storage word within 64: chunk (ks>>2)*32 + t4*8 + (ks&3)*2 (pair)
            int bb = (ks >> 2) * 128 + t4 * 32 + (ks & 3) * 8;
#pragma unroll
            for (int ni = 0; ni < 8; ni++) {
                int rn = nbase + ni * 8 + g;
                uint2 pb = *(uint2*)(Bc + rn * TFROW_B + bb);
#pragma unroll
                for (int mi = 0; mi < 2; mi++)
                    MMA_TF32(acc[mi][ni], a[mi][0], a[mi][1], a[mi][2], a[mi][3], pb.x, pb.y);
            }
        }
        if (more) {
            tf_commitA(nxt, tid, va);
            tf_commitB(nxt + TFTILE_A, tid, vb);
        }
        __syncthreads();
    }

#pragma unroll
    for (int mi = 0; mi < 2; mi++)
#pragma unroll
        for (int ni = 0; ni < 8; ni++) {
            int gm = m0 + mbase + mi * 16 + g;
            int gn = n0 + nbase + ni * 8 + t4 * 2;
            const float* c = acc[mi][ni];
#pragma unroll
            for (int hrow = 0; hrow < 2; hrow++) {
                long long ci = (long long)(gm + hrow * 8) * ldc + gn;
#pragma unroll
                for (int j = 0; j < 2; j++) {
                    float v = c[hrow * 2 + j] * scale;
                    if (EPI == 1)      v += bias[gn + j];
                    else if (EPI == 2) v = 1.f / (1.f + expf(-(v + bias[gn + j])));
                    else if (EPI == 3) v += bias[gn + j] + Cm[ci + j];
                    Cm[ci + j] = v;
                }
            }
        }
}

// =====================================================================
//     attention scores: S = Q K^T / 8  (split-bf16, K=64, z = b*H+h)
// =====================================================================
__global__ void __launch_bounds__(256, 1) attn_sc_k(
    const float* __restrict__ qkv, const float* __restrict__ kf,
    float* __restrict__ sc)
{
    extern __shared__ char smem[];
    int z = blockIdx.z, b = z >> 4, h = z & 15;
    int m0 = blockIdx.y * 128, n0 = blockIdx.x * 128;
    const float* A  = qkv + (long long)b * C_ * 3072 + h * 64;
    const float* Bp = kf + (long long)b * PC_ * D_ + h * 64;
    int tid = threadIdx.x, wid = tid >> 5, lid = tid & 31;

#pragma unroll
    for (int kc = 0; kc < 2; kc++) {
        float4 va[4];
        issue_f32<0>(A, 3072, m0, kc * 32, tid, va);
        commit_f32<0>(smem + kc * 2 * TILE_B, smem + kc * 2 * TILE_B + TILE_B, tid, va);
        int r = tid >> 1, hh = tid & 1;
        int j = n0 + r;
        float4 vb[4];
        if (j < PC_) {
#pragma unroll
            for (int i = 0; i < 4; i++)
                vb[i] = *(const float4*)(Bp + (long long)j * D_ + kc * 32 + hh * 16 + i * 4);
        } else {
#pragma unroll
            for (int i = 0; i < 4; i++) vb[i] = make_float4(0.f, 0.f, 0.f, 0.f);
        }
        commit_f32<0>(smem + (4 + kc * 2) * TILE_B, smem + (4 + kc * 2) * TILE_B + TILE_B, tid, vb);
    }
    __syncthreads();

    int g = lid >> 2, t4 = lid & 3;
    int mbase = (wid & 3) * 32, nbase = (wid >> 2) * 64;
    float acc[2][8][4];
#pragma unroll
    for (int mi = 0; mi < 2; mi++)
#pragma unroll
        for (int ni = 0; ni < 8; ni++)
#pragma unroll
            for (int j = 0; j < 4; j++) acc[mi][ni][j] = 0.f;

#pragma unroll
    for (int kc = 0; kc < 2; kc++) {
        char* Ah = smem + kc * 2 * TILE_B;       char* Al = Ah + TILE_B;
        char* Bh = smem + (4 + kc * 2) * TILE_B; char* Bl = Bh + TILE_B;
#pragma unroll
        for (int k16 = 0; k16 < 2; k16++) {
            int kcc = k16 * 16;
            uint32_t ah[2][4], al[2][4];
#pragma unroll
            for (int mi = 0; mi < 2; mi++) {
                int r = mbase + mi * 16 + g;
                int c = kcc + t4 * 2;
                ah[mi][0] = *(uint32_t*)(Ah + r * 80 + c * 2);
                ah[mi][1] = *(uint32_t*)(Ah + (r + 8) * 80 + c * 2);
                ah[mi][2] = *(uint32_t*)(Ah + r * 80 + (c + 8) * 2);
                ah[mi][3] = *(uint32_t*)(Ah + (r + 8) * 80 + (c + 8) * 2);
                al[mi][0] = *(uint32_t*)(Al + r * 80 + c * 2);
                al[mi][1] = *(uint32_t*)(Al + (r + 8) * 80 + c * 2);
                al[mi][2] = *(uint32_t*)(Al + r * 80 + (c + 8) * 2);
                al[mi][3] = *(uint32_t*)(Al + (r + 8) * 80 + (c + 8) * 2);
            }
#pragma unroll
            for (int ni = 0; ni < 8; ni++) {
                int r = nbase + ni * 8 + g;
                int c = kcc + t4 * 2;
                uint32_t bh0 = *(uint32_t*)(Bh + r * 80 + c * 2);
                uint32_t bh1 = *(uint32_t*)(Bh + r * 80 + (c + 8) * 2);
                uint32_t bl0 = *(uint32_t*)(Bl + r * 80 + c * 2);
                uint32_t bl1 = *(uint32_t*)(Bl + r * 80 + (c + 8) * 2);
#pragma unroll
                for (int mi = 0; mi < 2; mi++) {
                    MMA_B16(acc[mi][ni], ah[mi][0], ah[mi][1], ah[mi][2], ah[mi][3], bh0, bh1);
                    MMA_B16(acc[mi][ni], ah[mi][0], ah[mi][1], ah[mi][2], ah[mi][3], bl0, bl1);
                    MMA_B16(acc[mi][ni], al[mi][0], al[mi][1], al[mi][2], al[mi][3], bh0, bh1);
                }
            }
        }
    }
#pragma unroll
    for (int mi = 0; mi < 2; mi++)
#pragma unroll
        for (int ni = 0; ni < 8; ni++) {
            int gm = m0 + mbase + mi * 16 + g;
            int gn = n0 + nbase + ni * 8 + t4 * 2;
            const float* c = acc[mi][ni];
#pragma unroll
            for (int hrow = 0; hrow < 2; hrow++) {
                long long ci = ((long long)z * C_ + gm + hrow * 8) * PCs + gn;
                sc[ci]     = c[hrow * 2 + 0] * 0.125f;
                sc[ci + 1] = c[hrow * 2 + 1] * 0.125f;
            }
        }
}

// =====================================================================
//     attention P@V: ao[s][h*64+d] = sum_j P[s][j] V[j][d]   (K=544)
// =====================================================================
__global__ void __launch_bounds__(256) attn_pv_k(
    const float* __restrict__ sc, const float* __restrict__ vf,
    float* __restrict__ ao)
{
    __shared__ char sP[2 * TILE_B];
    __shared__ char sV[2 * 5120];
    int z = blockIdx.y, b = z >> 4, h = z & 15;
    int m0 = blockIdx.x * 128;
    const float* P = sc + ((long long)z * C_ + m0) * PCs;
    const float* V = vf + (long long)b * PC_ * D_ + h * 64;
    int tid = threadIdx.x, wid = tid >> 5, lid = tid & 31;
    int g = lid >> 2, t4 = lid & 3;

    float acc[8][4];
#pragma unroll
    for (int ni = 0; ni < 8; ni++)
#pragma unroll
        for (int j = 0; j < 4; j++) acc[ni][j] = 0.f;

    for (int kt = 0; kt < 17; kt++) {
        int k0 = kt * 32;
        float4 vp[4];
        issue_f32<0>(P, PCs, 0, k0, tid, vp);
        int jj = tid >> 3, d0 = (tid & 7) * 8;
        int j = k0 + jj;
        float4 v0 = make_float4(0.f, 0.f, 0.f, 0.f), v1 = v0;
        if (j < PC_) {
            v0 = *(const float4*)(V + (long long)j * D_ + d0);
            v1 = *(const float4*)(V + (long long)j * D_ + d0 + 4);
        }
        __syncthreads();
        commit_f32<0>(sP, sP + TILE_B, tid, vp);
        {
            float xs[8] = {v0.x, v0.y, v0.z, v0.w, v1.x, v1.y, v1.z, v1.w};
#pragma unroll
            for (int e = 0; e < 8; e++) {
                int d = d0 + e;
                __nv_bfloat16 hh, ll;
                cvt2(xs[e], hh, ll);
                *(__nv_bfloat16*)(sV + d * 80 + jj * 2) = hh;
                *(__nv_bfloat16*)(sV + 5120 + d * 80 + jj * 2) = ll;
            }
        }
        __syncthreads();
#pragma unroll
        for (int k16 = 0; k16 < 2; k16++) {
            int c = k16 * 16 + t4 * 2;
            int r = wid * 16 + g;
            uint32_t ph[4], pl[4];
            ph[0] = *(uint32_t*)(sP + r * 80 + c * 2);
            ph[1] = *(uint32_t*)(sP + (r + 8) * 80 + c * 2);
            ph[2] = *(uint32_t*)(sP + r * 80 + (c + 8) * 2);
            ph[3] = *(uint32_t*)(sP + (r + 8) * 80 + (c + 8) * 2);
            pl[0] = *(uint32_t*)(sP + TILE_B + r * 80 + c * 2);
            pl[1] = *(uint32_t*)(sP + TILE_B + (r + 8) * 80 + c * 2);
            pl[2] = *(uint32_t*)(sP + TILE_B + r * 80 + (c + 8) * 2);
            pl[3] = *(uint32_t*)(sP + TILE_B + (r + 8) * 80 + (c + 8) * 2);
#pragma unroll
            for (int ni = 0; ni < 8; ni++) {
                int d = ni * 8 + g;
                uint32_t bh0 = *(uint32_t*)(sV + d * 80 + c * 2);
                uint32_t bh1 = *(uint32_t*)(sV + d * 80 + (c + 8) * 2);
                uint32_t bl0 = *(uint32_t*)(sV + 5120 + d * 80 + c * 2);
                uint32_t bl1 = *(uint32_t*)(sV + 5120 + d * 80 + (c + 8) * 2);
                MMA_B16(acc[ni], ph[0], ph[1], ph[2], ph[3], bh0, bh1);
                MMA_B16(acc[ni], ph[0], ph[1], ph[2], ph[3], bl0, bl1);
                MMA_B16(acc[ni], pl[0], pl[1], pl[2], pl[3], bh0, bh1);
            }
        }
    }
#pragma unroll
    for (int ni = 0; ni < 8; ni++) {
        int gm = m0 + wid * 16 + g;
        int gn = ni * 8 + t4 * 2;
        float* o = ao + ((long long)b * C_ + gm) * D_ + h * 64 + gn;
        o[0] = acc[ni][0]; o[1] = acc[ni][1];
        float* o2 = o + 8 * D_;
        o2[0] = acc[ni][2]; o2[1] = acc[ni][3];
    }
}

// ---------------- block reductions ----------------
__device__ __forceinline__ float blockReduceSum(float v) {
    __shared__ float sh[33];
    int lane = threadIdx.x & 31, w = threadIdx.x >> 5, nw = blockDim.x >> 5;
#pragma unroll
    for (int o = 16; o; o >>= 1) v += __shfl_xor_sync(0xffffffffu, v, o);
    __syncthreads();
    if (lane == 0) sh[w] = v;
    __syncthreads();
    if (w == 0) {
        float t = (lane < nw) ? sh[lane] : 0.f;
#pragma unroll
        for (int o = 16; o; o >>= 1) t += __shfl_xor_sync(0xffffffffu, t, o);
        if (lane == 0) sh[32] = t;
    }
    __syncthreads();
    return sh[32];
}

// ---------------- layernorm ----------------
__global__ void ln_kernel(const float* __restrict__ xin, int gather, int c0,
                          const float* __restrict__ add,
                          const float* __restrict__ gamma, const float* __restrict__ beta,
                          float* __restrict__ out)
{
    int t = blockIdx.x;
    const float* px;
    if (gather) {
        int b = t >> 9, s = t & 511;
        px = xin + ((size_t)b * S_ + c0 + s) * D_;
    } else {
        px = xin + (size_t)t * D_;
    }
    int i0 = threadIdx.x * 4;
    float4 v = *(const float4*)(px + i0);
    if (add) {
        float4 a = *(const float4*)(add + (size_t)t * D_ + i0);
        v.x += a.x; v.y += a.y; v.z += a.z; v.w += a.w;
    }
    float mean = blockReduceSum(v.x + v.y + v.z + v.w) * (1.f / D_);
    float dx = v.x - mean, dy = v.y - mean, dz = v.z - mean, dw = v.w - mean;
    float var = blockReduceSum(dx*dx + dy*dy + dz*dz + dw*dw) * (1.f / D_);
    float inv = rsqrtf(var + 1e-5f);
    float4 gv = *(const float4*)(gamma + i0);
    float4 bv = *(const float4*)(beta + i0);
    float4 o;
    o.x = dx * inv * gv.x + bv.x;
    o.y = dy * inv * gv.y + bv.y;
    o.z = dz * inv * gv.z + bv.z;
    o.w = dw * inv * gv.w + bv.w;
    *(float4*)(out + (size_t)t * D_ + i0) = o;
}

__global__ void rownorm_kernel(float* __restrict__ a, int ld, int off) {
    int t = blockIdx.x;
    float* p = a + (size_t)t * ld + off;
    int i0 = threadIdx.x * 4;
    float4 v = *(const float4*)(p + i0);
    float ss = blockReduceSum(v.x*v.x + v.y*v.y + v.z*v.z + v.w*v.w);
    float inv = rsqrtf(ss + 1e-6f);
    v.x *= inv; v.y *= inv; v.z *= inv; v.w *= inv;
    *(float4*)(p + i0) = v;
}

// warp-per-row softmax: block=256 handles 8 rows
__global__ void softmax_kernel(float* __restrict__ sc) {
    int row = blockIdx.x * 8 + (threadIdx.x >> 5);
    int lane = threadIdx.x & 31;
    int i = row & (C_ - 1);
    int valid = P_ + i + 1;
    float* r = sc + (size_t)row * PCs;
    float mx = -1e30f;
    for (int j = lane; j < valid; j += 32) mx = fmaxf(mx, r[j]);
#pragma unroll
    for (int o = 16; o; o >>= 1) mx = fmaxf(mx, __shfl_xor_sync(0xffffffffu, mx, o));
    float s = 0.f;
    for (int j = lane; j < valid; j += 32) { float e = expf(r[j] - mx); r[j] = e; s += e; }
#pragma unroll
    for (int o = 16; o; o >>= 1) s += __shfl_xor_sync(0xffffffffu, s, o);
    float inv = 1.f / s;
    for (int j = lane; j < PCs; j += 32) r[j] = (j < valid) ? r[j] * inv : 0.f;
}

__global__ void pack_kernel(const float* __restrict__ pk, const float* __restrict__ pv,
                            const float* __restrict__ qkv,
                            float* __restrict__ kf, float* __restrict__ vf)
{
    int bj = blockIdx.x;
    int b = bj / PC_, j = bj - b * PC_;
    size_t dst = (size_t)bj * D_ + threadIdx.x * 4;
    float4 kq, vq;
    if (j < P_) {
        kq = *(const float4*)(pk + (size_t)j * D_ + threadIdx.x * 4);
        vq = *(const float4*)(pv + (size_t)j * D_ + threadIdx.x * 4);
    } else {
        size_t row = ((size_t)b * C_ + (j - P_)) * 3072;
        kq = *(const float4*)(qkv + row + 1024 + threadIdx.x * 4);
        vq = *(const float4*)(qkv + row + 2048 + threadIdx.x * 4);
    }
    *(float4*)(kf + dst) = kq;
    *(float4*)(vf + dst) = vq;
}

__global__ void zero2_kernel(float4* a, float4* b, int n4) {
    int i = blockIdx.x * blockDim.x + threadIdx.x;
    float4 z = make_float4(0.f, 0.f, 0.f, 0.f);
    if (i < n4) { a[i] = z; b[i] = z; }
}
__global__ void sub_kernel(float4* __restrict__ a, const float* __restrict__ b) {
    int i = blockIdx.x * blockDim.x + threadIdx.x;   // NTOK*D/4
    int t = i >> 8, d = (i & 255) * 4;
    float4 av = a[i];
    float4 bv = *(const float4*)(b + (size_t)t * 3072 + 2048 + d);
    av.x -= bv.x; av.y -= bv.y; av.z -= bv.z; av.w -= bv.w;
    a[i] = av;
}
__global__ void update_kernel(float4* __restrict__ M, float4* __restrict__ St,
                              const float4* __restrict__ grad,
                              const float* lr, const float* mom, const float* fg, int n4) {
    float theta = 1.f / (1.f + expf(-lr[0]));
    float eta   = 1.f / (1.f + expf(-mom[0]));
    float alpha = 1.f / (1.f + expf(-fg[0]));
    int i = blockIdx.x * blockDim.x + threadIdx.x;
    if (i < n4) {
        float4 st = St[i], gr = grad[i], m = M[i];
        st.x = eta * st.x - theta * gr.x;
        st.y = eta * st.y - theta * gr.y;
        st.z = eta * st.z - theta * gr.z;
        st.w = eta * st.w - theta * gr.w;
        St[i] = st;
        m.x = (1.f - alpha) * m.x + st.x;
        m.y = (1.f - alpha) * m.y + st.y;
        m.z = (1.f - alpha) * m.z + st.z;
        m.w = (1.f - alpha) * m.w + st.w;
        M[i] = m;
    }
}
__global__ void combine_kernel(const float* __restrict__ x, const float4* __restrict__ gt,
                               const float4* __restrict__ ap, const float4* __restrict__ mem,
                               float* __restrict__ out, int c0) {
    int i = blockIdx.x * blockDim.x + threadIdx.x;   // NTOK*D/4
    int t = i >> 8, d = (i & 255) * 4;
    int b = t >> 9, s = t & 511;
    size_t xi = ((size_t)b * S_ + c0 + s) * D_ + d;
    float4 xv = *(const float4*)(x + xi);
    float4 g = gt[i], a = ap[i], m = mem[i];
    float4 o;
    o.x = xv.x + g.x * a.x + (1.f - g.x) * m.x;
    o.y = xv.y + g.y * a.y + (1.f - g.y) * m.y;
    o.z = xv.z + g.z * a.z + (1.f - g.z) * m.z;
    o.w = xv.w + g.w * a.w + (1.f - g.w) * m.w;
    *(float4*)(out + xi) = o;
}
__global__ void silu_kernel(float* __restrict__ ff) {
    int i = blockIdx.x * blockDim.x + threadIdx.x;   // NTOK*FF/4
    int t = i >> 10, d = (i & 1023) * 4;
    size_t o = (size_t)t * 8192 + d;
    float4 a = *(const float4*)(ff + o);
    float4 b = *(const float4*)(ff + o + 4096);
    a.x = a.x / (1.f + expf(-a.x)) * b.x;
    a.y = a.y / (1.f + expf(-a.y)) * b.y;
    a.z = a.z / (1.f + expf(-a.z)) * b.z;
    a.w = a.w / (1.f + expf(-a.w)) * b.w;
    *(float4*)(ff + o) = a;
}

// ---------------- host side ----------------
static float* symaddr(const void* s) {
    void* p = nullptr;
    cudaGetSymbolAddress(&p, s);
    return (float*)p;
}

template<int TRA, int TRB, int EPI>
static void mm(const float* A, const float* Bf, const float* bias, float* Cm,
               int M, int N, int K, long long lda, long long ldb, long long ldc,
               float scale, int Z, int zdiv,
               long long aO, long long aI, long long bO, long long bI,
               long long cO, long long cI)
{
    cudaFuncSetAttribute(mm_k<TRA, TRB, EPI>,
                         cudaFuncAttributeMaxDynamicSharedMemorySize, SMEM_MM);
    dim3 grid(N / 128, M / 128, Z);
    mm_k<TRA, TRB, EPI><<<grid, 256, SMEM_MM>>>(
        A, Bf, bias, Cm, M, N, K, lda, ldb, ldc, scale, zdiv,
        aO, aI, bO, bI, cO, cI);
}

template<int EPI>
static void mmtf(const float* A, const uint32_t* W, const float* bias, float* Cm,
                 int M, int N, int K, long long lda, long long ldc, float scale,
                 int Z, long long aO, long long cO)
{
    cudaFuncSetAttribute(mmtf_k<EPI>,
                         cudaFuncAttributeMaxDynamicSharedMemorySize, SMEM_TF);
    dim3 grid(N / 128, M / 128, Z);
    mmtf_k<EPI><<<grid, 256, SMEM_TF>>>(A, W, bias, Cm, M, N, K, lda, ldc,
                                        scale, aO, cO);
}

extern "C" void kernel_launch(void* const* d_in, const int* in_sizes, int n_in,
                              void* d_out, int out_size)
{
    const float* x     = (const float*)d_in[0];
    const float* g1    = (const float*)d_in[1];
    const float* b1    = (const float*)d_in[2];
    const float* g2    = (const float*)d_in[3];
    const float* b2p   = (const float*)d_in[4];
    const float* g3    = (const float*)d_in[5];
    const float* b3    = (const float*)d_in[6];
    const float* Wqm   = (const float*)d_in[7];
    const float* Wkm   = (const float*)d_in[8];
    const float* Wvm   = (const float*)d_in[9];
    const float* lr    = (const float*)d_in[10];
    const float* mom   = (const float*)d_in[11];
    const float* fg    = (const float*)d_in[12];
    const float* Wq    = (const float*)d_in[13];
    const float* bq    = (const float*)d_in[14];
    const float* Wk    = (const float*)d_in[15];
    const float* bk    = (const float*)d_in[16];
    const float* Wv    = (const float*)d_in[17];
    const float* bv    = (const float*)d_in[18];
    const float* Wo    = (const float*)d_in[19];
    const float* bo    = (const float*)d_in[20];
    const float* pk    = (const float*)d_in[21];
    const float* pv    = (const float*)d_in[22];
    const float* Wg    = (const float*)d_in[23];
    const float* bg    = (const float*)d_in[24];
    const float* Wgate = (const float*)d_in[25];
    const float* bgate = (const float*)d_in[26];
    const float* Wup   = (const float*)d_in[27];
    const float* bup   = (const float*)d_in[28];
    const float* Wdown = (const float*)d_in[29];
    const float* bdown = (const float*)d_in[30];
    float* out = (float*)d_out;

    float* pM   = symaddr(g_M);
    float* pSt  = symaddr(g_St);
    float* pGr  = symaddr(g_grad);
    float* ph1  = symaddr(g_h1);
    float* pmm3 = symaddr(g_mm3);
    float* pmp  = symaddr(g_mp);
    float* pmem = pmp;
    float* ppr  = pmp + (size_t)NTOK * D_;
    float* ph2  = symaddr(g_h2);
    float* pqkv = symaddr(g_qkv);
    float* pkf  = symaddr(g_kf);
    float* pvf  = symaddr(g_vf);
    float* psc  = symaddr(g_sc);
    float* pao  = symaddr(g_ao);
    float* pap  = symaddr(g_ap);
    float* pgt  = symaddr(g_gt);
    float* ph3  = symaddr(g_h3);
    float* pff  = symaddr(g_ff);
    float* pb3  = symaddr(g_bias3);
    float* pbff = symaddr(g_biasff);
    uint32_t* wt = (uint32_t*)symaddr(g_wt);

    const long long oWqm = 0, oWq = 3145728,
                    oWo = 6291456, oWg = 7340032,
                    oWgate = 8388608, oWdown = 16777216;

    dim3 blk(32, 8);
    wtf32_k<<<dim3(D_/32, D_/32), blk>>>(Wqm, wt + oWqm,           D_, D_);
    wtf32_k<<<dim3(D_/32, D_/32), blk>>>(Wkm, wt + oWqm + 1048576, D_, D_);
    wtf32_k<<<dim3(D_/32, D_/32), blk>>>(Wvm, wt + oWqm + 2097152, D_, D_);

    const int BDD = B_ * D_ * D_;
    zero2_kernel<<<(BDD/4 + 255) / 256, 256>>>((float4*)pM, (float4*)pSt, BDD/4);

    const long long CD  = (long long)C_ * D_;
    const long long DD  = (long long)D_ * D_;

    cudaFuncSetAttribute(attn_sc_k, cudaFuncAttributeMaxDynamicSharedMemorySize, SMEM_MM);

    for (int c = 0; c < NCH; c++) {
        int c0 = c * C_;

        ln_kernel<<<NTOK, 256>>>(x, 1, c0, nullptr, g1, b1, ph1);

        // merged neural-memory projections (tf32)
        mmtf<0>(ph1, wt + oWqm, nullptr, pmm3, NTOK, 3072, D_, D_, 3072, 1.f, 1, 0, 0);

        if (c == 0) {
            wtf32_k<<<dim3(D_/32, D_/32),  blk>>>(Wq,    wt + oWq,              D_, D_);
            wtf32_k<<<dim3(D_/32, D_/32),  blk>>>(Wk,    wt + oWq + 1048576,    D_, D_);
            wtf32_k<<<dim3(D_/32, D_/32),  blk>>>(Wv,    wt + oWq + 2097152,    D_, D_);
            wtf32_k<<<dim3(D_/32, D_/32),  blk>>>(Wo,    wt + oWo,              D_, D_);
            wtf32_k<<<dim3(D_/32, D_/32),  blk>>>(Wg,    wt + oWg,              D_, D_);
            wtf32_k<<<dim3(FF_/32, D_/32), blk>>>(Wgate, wt + oWgate,           D_, FF_);
            wtf32_k<<<dim3(FF_/32, D_/32), blk>>>(Wup,   wt + oWgate + 4194304, D_, FF_);
            wtf32_k<<<dim3(D_/32, FF_/32), blk>>>(Wdown, wt + oWdown,           FF_, D_);
            cat3_k<<<12, 256>>>(bq, bk, bv, pb3);
            cat2_k<<<32, 256>>>(bgate, bup, pbff);
        }

        rownorm_kernel<<<NTOK, 256>>>(pmm3, 3072, 1024);

        // mem/pred (bf16 split, recurrence-sensitive)
        mm<0,0,0>(pmm3, pM, nullptr, pmp, C_, D_, D_,
                  3072, D_, D_, 1.f, 8, 4,
                  1024, (long long)C_ * 3072, 0, DD,
                  (long long)NTOK * D_, CD);

        sub_kernel<<<(NTOK * D_ / 4 + 255) / 256, 256>>>((float4*)ppr, pmm3);
        mm<1,1,0>(ppr, pmm3 + 1024, nullptr, pGr, D_, D_, C_,
                  D_, 3072, D_, 1.f / C_, B_, 1,
                  CD, 0, (long long)C_ * 3072, 0, DD, 0);

        update_kernel<<<(BDD/4 + 255) / 256, 256>>>((float4*)pM, (float4*)pSt,
                                                    (const float4*)pGr, lr, mom, fg, BDD/4);

        ln_kernel<<<NTOK, 256>>>(x, 1, c0, pmem, g2, b2p, ph2);

        // merged q,k,v (tf32)
        mmtf<1>(ph2, wt + oWq, pb3, pqkv, NTOK, 3072, D_, D_, 3072, 1.f, 1, 0, 0);

        pack_kernel<<<B_ * PC_, 256>>>(pk, pv, pqkv, pkf, pvf);

        attn_sc_k<<<dim3(5, 4, B_ * H_), 256, SMEM_MM>>>(pqkv, pkf, psc);
        softmax_kernel<<<B_ * H_ * C_ / 8, 256>>>(psc);
        attn_pv_k<<<dim3(4, B_ * H_), 256>>>(psc, pvf, pao);

        mmtf<1>(pao,  wt + oWo, bo, pap, NTOK, D_, D_, D_, D_, 1.f, 1, 0, 0);
        mmtf<2>(pmem, wt + oWg, bg, pgt, NTOK, D_, D_, D_, D_, 1.f, 1, 0, 0);

        combine_kernel<<<(NTOK * D_ / 4 + 255) / 256, 256>>>(x, (const float4*)pgt,
                                                             (const float4*)pap,
                                                             (const float4*)pmem, out, c0);

        ln_kernel<<<NTOK, 256>>>(out, 1, c0, nullptr, g3, b3, ph3);
        mmtf<1>(ph3, wt + oWgate, pbff, pff, NTOK, 8192, D_, D_, 8192, 1.f, 1, 0, 0);
        silu_kernel<<<(NTOK * FF_ / 4 + 255) / 256, 256>>>(pff);
        mmtf<3>(pff, wt + oWdown, bdown, out + (size_t)c0 * D_,
                C_, D_, FF_, 8192, D_, 1.f, B_,
                (long long)C_ * 8192, (long long)S_ * D_);
    }
}

// round 15
// speedup vs baseline: 1.1121x; 1.1121x over previous
#include <cuda_runtime.h>
#include <cuda_bf16.h>
#include <math.h>
#include <stdint.h>

// ---------------- problem constants ----------------
#define B_   4
#define S_   4096
#define D_   1024
#define H_   16
#define DH_  64
#define P_   16
#define C_   512
#define FF_  4096
#define NTOK 2048      /* B_*C_ tokens per chunk */
#define PC_  528       /* P_ + C_ */
#define PCs  640       /* padded score stride */
#define NCH  8         /* S_/C_ chunks */

// ---------------- device scratch (no allocation allowed) ----------------
__device__ float g_M   [(size_t)B_*D_*D_];      // TRANSPOSED: Mt[v][k] = M[k][v]
__device__ float g_St  [(size_t)B_*D_*D_];
__device__ float g_grad[(size_t)B_*D_*D_];
__device__ float g_h1  [(size_t)NTOK*D_];
__device__ float g_mm3 [(size_t)NTOK*3072];     // [qm|km|vm] ld=3072
__device__ float g_mp  [(size_t)2*NTOK*D_];     // [mem_ctx ; pred-vm] contiguous
__device__ float g_h2  [(size_t)NTOK*D_];
__device__ float g_qkv [(size_t)NTOK*3072];     // [qh|kh|vh] ld=3072
__device__ float g_kf  [(size_t)B_*PC_*D_];
__device__ float g_vf  [(size_t)B_*PC_*D_];
__device__ float g_sc  [(size_t)B_*H_*C_*PCs];
__device__ float g_ao  [(size_t)NTOK*D_];
__device__ float g_ap  [(size_t)NTOK*D_];
__device__ float g_gt  [(size_t)NTOK*D_];
__device__ float g_h3  [(size_t)NTOK*D_];
__device__ float g_ff  [(size_t)NTOK*8192];     // [gate|up] ld=8192
__device__ float g_bias3 [3072];
__device__ float g_biasff[8192];
// pre-transposed weights [N,K] in tf32 (u32), k pair-permuted per 32-chunk
#define WTOT 20971520
__device__ uint32_t g_wt[WTOT];

__device__ __forceinline__ void cvt2(float x, __nv_bfloat16& h, __nv_bfloat16& l) {
    h = __float2bfloat16(x);
    l = __float2bfloat16(x - __bfloat162float(h));
}
__device__ __forceinline__ uint32_t f2tf(float x) {
    uint32_t r; asm("cvt.rna.tf32.f32 %0, %1;" : "=r"(r) : "f"(x)); return r;
}

// =====================================================================
//   weight transpose+tf32:  src[K,N] fp32 -> dst[N,K] tf32,
//   k pair-permuted within 32-word chunks
// =====================================================================
__global__ void wtf32_k(const float* __restrict__ src, uint32_t* __restrict__ dst,
                        int K, int N)
{
    __shared__ float t[32][33];
    int nb = blockIdx.x * 32, kb = blockIdx.y * 32;
    int tx = threadIdx.x, ty = threadIdx.y;
#pragma unroll
    for (int i = 0; i < 32; i += 8)
        t[ty + i][tx] = src[(long long)(kb + ty + i) * N + nb + tx];
    __syncthreads();
    int ks = tx >> 3, rem = tx & 7;
    int s_local = (rem & 3) * 8 + ks * 2 + (rem >> 2);
#pragma unroll
    for (int i = 0; i < 32; i += 8) {
        long long o = (long long)(nb + ty + i) * K + kb + s_local;
        dst[o] = f2tf(t[tx][ty + i]);
    }
}

__global__ void cat3_k(const float* a, const float* b, const float* c, float* d) {
    int i = blockIdx.x * 256 + threadIdx.x;
    d[i] = (i < 1024) ? a[i] : (i < 2048) ? b[i - 1024] : c[i - 2048];
}
__global__ void cat2_k(const float* a, const float* b, float* d) {
    int i = blockIdx.x * 256 + threadIdx.x;
    d[i] = (i < 4096) ? a[i] : b[i - 4096];
}

// =====================================================================
//      bf16 split GEMM (state GEMMs): block 128x128x32, 8 warps
// =====================================================================
#define TILE_B 10240              /* 128 rows x 80 bytes */
#define SMEM_MM (8*TILE_B)        /* 81920 */

#define MMA_B16(c, a0, a1, a2, a3, b0, b1)                                     \
    asm volatile("mma.sync.aligned.m16n8k16.row.col.f32.bf16.bf16.f32 "        \
                 "{%0,%1,%2,%3}, {%4,%5,%6,%7}, {%8,%9}, {%0,%1,%2,%3};"       \
                 : "+f"(c[0]), "+f"(c[1]), "+f"(c[2]), "+f"(c[3])              \
                 : "r"(a0), "r"(a1), "r"(a2), "r"(a3), "r"(b0), "r"(b1))

#define MMA_TF32(c, a0, a1, a2, a3, b0, b1)                                    \
    asm volatile("mma.sync.aligned.m16n8k8.row.col.f32.tf32.tf32.f32 "         \
                 "{%0,%1,%2,%3}, {%4,%5,%6,%7}, {%8,%9}, {%0,%1,%2,%3};"       \
                 : "+f"(c[0]), "+f"(c[1]), "+f"(c[2]), "+f"(c[3])              \
                 : "r"(a0), "r"(a1), "r"(a2), "r"(a3), "r"(b0), "r"(b1))

// ---- fp32 loaders (bf16 hi/lo commit) ----
template<int TR>
__device__ __forceinline__ void issue_f32(const float* __restrict__ src, long long ld,
                                          int row0, int k0, int tid, float4 v[4]) {
    if (TR == 0) {
        int r = tid >> 1, h = tid & 1;
#pragma unroll
        for (int i = 0; i < 4; i++)
            v[i] = *(const float4*)(src + (long long)(row0 + r) * ld + k0 + h * 16 + i * 4);
    } else {
        int kk = tid >> 3, q = tid & 7;
#pragma unroll
        for (int i = 0; i < 4; i++)
            v[i] = *(const float4*)(src + (long long)(k0 + kk) * ld + row0 + (q + i * 8) * 4);
    }
}
template<int TR>
__device__ __forceinline__ void commit_f32(char* dhi, char* dlo, int tid, const float4 v[4]) {
    if (TR == 0) {
        int r = tid >> 1, h = tid & 1;
#pragma unroll
        for (int i = 0; i < 4; i++) {
            int c = h * 16 + i * 4;
            __nv_bfloat16 h0, h1, h2, h3, l0, l1, l2, l3;
            cvt2(v[i].x, h0, l0); cvt2(v[i].y, h1, l1);
            cvt2(v[i].z, h2, l2); cvt2(v[i].w, h3, l3);
            uint2 hp, lp;
            hp.x = (uint32_t)__bfloat16_as_ushort(h0) | ((uint32_t)__bfloat16_as_ushort(h1) << 16);
            hp.y = (uint32_t)__bfloat16_as_ushort(h2) | ((uint32_t)__bfloat16_as_ushort(h3) << 16);
            lp.x = (uint32_t)__bfloat16_as_ushort(l0) | ((uint32_t)__bfloat16_as_ushort(l1) << 16);
            lp.y = (uint32_t)__bfloat16_as_ushort(l2) | ((uint32_t)__bfloat16_as_ushort(l3) << 16);
            *(uint2*)(dhi + r * 80 + c * 2) = hp;
            *(uint2*)(dlo + r * 80 + c * 2) = lp;
        }
    } else {
        int kk = tid >> 3, q = tid & 7;
#pragma unroll
        for (int i = 0; i < 4; i++) {
            int m = (q + i * 8) * 4;
            float xs[4] = {v[i].x, v[i].y, v[i].z, v[i].w};
#pragma unroll
            for (int j = 0; j < 4; j++) {
                __nv_bfloat16 h, l;
                cvt2(xs[j], h, l);
                *(__nv_bfloat16*)(dhi + (m + j) * 80 + kk * 2) = h;
                *(__nv_bfloat16*)(dlo + (m + j) * 80 + kk * 2) = l;
            }
        }
    }
}

// EPI: 0=store 1=+bias 2=sigmoid(+bias) 3=accum(+bias) 4=store, pred-half minus vm
template<int TRA, int TRB, int EPI>
__global__ void __launch_bounds__(256, 1) mm_k(
    const float* __restrict__ A, const float* __restrict__ Bf,
    const float* __restrict__ bias, float* __restrict__ Cm,
    int M, int N, int K, long long lda, long long ldb, long long ldc, float scale,
    int zdiv,
    long long aO, long long aI, long long bO, long long bI, long long cO, long long cI)
{
    extern __shared__ char smem[];
    int z = blockIdx.z;
    int zq = z / zdiv, zr = z % zdiv;
    A  += zq * aO + zr * aI;
    Bf += zq * bO + zr * bI;
    Cm += zq * cO + zr * cI;

    int tid = threadIdx.x, wid = tid >> 5, lid = tid & 31;
    int m0 = blockIdx.y * 128, n0 = blockIdx.x * 128;

    float acc[2][8][4];
#pragma unroll
    for (int mi = 0; mi < 2; mi++)
#pragma unroll
        for (int ni = 0; ni < 8; ni++)
#pragma unroll
            for (int j = 0; j < 4; j++) acc[mi][ni][j] = 0.f;

    {
        float4 va[4], vb[4];
        issue_f32<TRA>(A, lda, m0, 0, tid, va);
        commit_f32<TRA>(smem, smem + TILE_B, tid, va);
        issue_f32<TRB>(Bf, ldb, n0, 0, tid, vb);
        commit_f32<TRB>(smem + 2 * TILE_B, smem + 3 * TILE_B, tid, vb);
    }
    __syncthreads();

    int g = lid >> 2, t4 = lid & 3;
    int mbase = (wid & 3) * 32, nbase = (wid >> 2) * 64;
    int KT = K / 32;

    for (int kt = 0; kt < KT; kt++) {
        char* cur = smem + (kt & 1) * 4 * TILE_B;
        char* nxt = smem + ((kt + 1) & 1) * 4 * TILE_B;
        float4 va[4], vb[4];
        bool more = (kt + 1 < KT);
        if (more) {
            issue_f32<TRA>(A, lda, m0, (kt + 1) * 32, tid, va);
            issue_f32<TRB>(Bf, ldb, n0, (kt + 1) * 32, tid, vb);
        }
        char* Ah = cur;              char* Al = cur + TILE_B;
        char* Bh = cur + 2 * TILE_B; char* Bl = cur + 3 * TILE_B;
#pragma unroll
        for (int k16 = 0; k16 < 2; k16++) {
            int kc = k16 * 16;
            uint32_t ah[2][4], al[2][4];
#pragma unroll
            for (int mi = 0; mi < 2; mi++) {
                int r = mbase + mi * 16 + g;
                int c = kc + t4 * 2;
                ah[mi][0] = *(uint32_t*)(Ah + r * 80 + c * 2);
                ah[mi][1] = *(uint32_t*)(Ah + (r + 8) * 80 + c * 2);
                ah[mi][2] = *(uint32_t*)(Ah + r * 80 + (c + 8) * 2);
                ah[mi][3] = *(uint32_t*)(Ah + (r + 8) * 80 + (c + 8) * 2);
                al[mi][0] = *(uint32_t*)(Al + r * 80 + c * 2);
                al[mi][1] = *(uint32_t*)(Al + (r + 8) * 80 + c * 2);
                al[mi][2] = *(uint32_t*)(Al + r * 80 + (c + 8) * 2);
                al[mi][3] = *(uint32_t*)(Al + (r + 8) * 80 + (c + 8) * 2);
            }
#pragma unroll
            for (int ni = 0; ni < 8; ni++) {
                int r = nbase + ni * 8 + g;
                int c = kc + t4 * 2;
                uint32_t bh0 = *(uint32_t*)(Bh + r * 80 + c * 2);
                uint32_t bh1 = *(uint32_t*)(Bh + r * 80 + (c + 8) * 2);
                uint32_t bl0 = *(uint32_t*)(Bl + r * 80 + c * 2);
                uint32_t bl1 = *(uint32_t*)(Bl + r * 80 + (c + 8) * 2);
#pragma unroll
                for (int mi = 0; mi < 2; mi++) {
                    MMA_B16(acc[mi][ni], ah[mi][0], ah[mi][1], ah[mi][2], ah[mi][3], bh0, bh1);
                    MMA_B16(acc[mi][ni], ah[mi][0], ah[mi][1], ah[mi][2], ah[mi][3], bl0, bl1);
                    MMA_B16(acc[mi][ni], al[mi][0], al[mi][1], al[mi][2], al[mi][3], bh0, bh1);
                }
            }
        }
        if (more) {
            commit_f32<TRA>(nxt, nxt + TILE_B, tid, va);
            commit_f32<TRB>(nxt + 2 * TILE_B, nxt + 3 * TILE_B, tid, vb);
        }
        __syncthreads();
    }

#pragma unroll
    for (int mi = 0; mi < 2; mi++)
#pragma unroll
        for (int ni = 0; ni < 8; ni++) {
            int gm = m0 + mbase + mi * 16 + g;
            int gn = n0 + nbase + ni * 8 + t4 * 2;
            const float* c = acc[mi][ni];
#pragma unroll
            for (int hrow = 0; hrow < 2; hrow++) {
                long long ci = (long long)(gm + hrow * 8) * ldc + gn;
#pragma unroll
                for (int j = 0; j < 2; j++) {
                    float v = c[hrow * 2 + j] * scale;
                    if (EPI == 1)      v += bias[gn + j];
                    else if (EPI == 2) v = 1.f / (1.f + expf(-(v + bias[gn + j])));
                    else if (EPI == 3) v += bias[gn + j] + Cm[ci + j];
                    else if (EPI == 4) {
                        if (zq == 1)   // pred half: subtract vm from bias=pmm3+2048 view
                            v -= bias[((long long)zr * C_ + gm + hrow * 8) * 3072 + gn + j];
                    }
                    Cm[ci + j] = v;
                }
            }
        }
}

// =====================================================================
//      TF32 single-pass weight GEMM (R12 config): block 128x128x32
//      A: linear layout, stride 144.  B: pair-permuted, stride 136.
//      SILU=1: A = silu(gate)*up computed on the fly (lda=8192, up at +4096)
// =====================================================================
#define TFROW_A 144
#define TFROW_B 136
#define TFTILE_A (128*TFROW_A)
#define TFTILE_B (128*TFROW_B)
#define TFSTAGE  (TFTILE_A+TFTILE_B)
#define SMEM_TF  (2*TFSTAGE)

template<int SILU>
__device__ __forceinline__ void tf_issueA(const float* __restrict__ src, long long ld,
                                          int row0, int k0, int tid,
                                          float4 v[4], float4 u[4]) {
    int r = tid >> 1, h = tid & 1;
#pragma unroll
    for (int i = 0; i < 4; i++) {
        const float* p = src + (long long)(row0 + r) * ld + k0 + h * 16 + i * 4;
        v[i] = *(const float4*)p;
        if (SILU) u[i] = *(const float4*)(p + 4096);
    }
}
template<int SILU>
__device__ __forceinline__ void tf_commitA(char* d, int tid,
                                           const float4 v[4], const float4 u[4]) {
    int r = tid >> 1, h = tid & 1;
#pragma unroll
    for (int i = 0; i < 4; i++) {
        float4 w = v[i];
        if (SILU) {
            w.x = w.x / (1.f + expf(-w.x)) * u[i].x;
            w.y = w.y / (1.f + expf(-w.y)) * u[i].y;
            w.z = w.z / (1.f + expf(-w.z)) * u[i].z;
            w.w = w.w / (1.f + expf(-w.w)) * u[i].w;
        }
        uint4 t;
        t.x = f2tf(w.x); t.y = f2tf(w.y); t.z = f2tf(w.z); t.w = f2tf(w.w);
        *(uint4*)(d + r * TFROW_A + (h * 16 + i * 4) * 4) = t;
    }
}
__device__ __forceinline__ void tf_issueB(const uint32_t* __restrict__ src, long long K,
                                          int n0, int k0, int tid, uint4 v[4]) {
    int r = tid >> 1, h = tid & 1;
#pragma unroll
    for (int i = 0; i < 4; i++)
        v[i] = *(const uint4*)(src + (long long)(n0 + r) * K + k0 + h * 16 + i * 4);
}
// 8B stores only (TFROW_B=136 not 16B-aligned for odd rows)
__device__ __forceinline__ void tf_commitB(char* d, int tid, const uint4 v[4]) {
    int r = tid >> 1, h = tid & 1;
    char* base = d + r * TFROW_B + h * 64;
#pragma unroll
    for (int i = 0; i < 4; i++) {
        *(uint2*)(base + i * 16)     = make_uint2(v[i].x, v[i].y);
        *(uint2*)(base + i * 16 + 8) = make_uint2(v[i].z, v[i].w);
    }
}

template<int EPI, int SILU>
__global__ void __launch_bounds__(256, 1) mmtf_k(
    const float* __restrict__ A, const uint32_t* __restrict__ W,
    const float* __restrict__ bias, float* __restrict__ Cm,
    int M, int N, int K, long long lda, long long ldc, float scale,
    long long aO, long long cO)
{
    extern __shared__ char smem[];
    int z = blockIdx.z;
    A  += (long long)z * aO;
    Cm += (long long)z * cO;

    int tid = threadIdx.x, wid = tid >> 5, lid = tid & 31;
    int m0 = blockIdx.y * 128, n0 = blockIdx.x * 128;

    float acc[2][8][4];
#pragma unroll
    for (int mi = 0; mi < 2; mi++)
#pragma unroll
        for (int ni = 0; ni < 8; ni++)
#pragma unroll
            for (int j = 0; j < 4; j++) acc[mi][ni][j] = 0.f;

    {
        float4 va[4], vu[4]; uint4 vb[4];
        tf_issueA<SILU>(A, lda, m0, 0, tid, va, vu);
        tf_commitA<SILU>(smem, tid, va, vu);
        tf_issueB(W, K, n0, 0, tid, vb);
        tf_commitB(smem + TFTILE_A, tid, vb);
    }
    __syncthreads();

    int g = lid >> 2, t4 = lid & 3;
    int mbase = (wid & 3) * 32, nbase = (wid >> 2) * 64;
    int KT = K / 32;

    for (int kt = 0; kt < KT; kt++) {
        char* cur = smem + (kt & 1) * TFSTAGE;
        char* nxt = smem + ((kt + 1) & 1) * TFSTAGE;
        float4 va[4], vu[4]; uint4 vb[4];
        bool more = (kt + 1 < KT);
        if (more) {
            tf_issueA<SILU>(A, lda, m0, (kt + 1) * 32, tid, va, vu);
            tf_issueB(W, K, n0, (kt + 1) * 32, tid, vb);
        }
        char* Ac = cur;
        char* Bc = cur + TFTILE_A;
#pragma unroll
        for (int ks = 0; ks < 4; ks++) {
            int kc = ks * 8;
            uint32_t a[2][4];
#pragma unroll
            for (int mi = 0; mi < 2; mi++) {
                int r = mbase + mi * 16 + g;
                a[mi][0] = *(uint32_t*)(Ac + r * TFROW_A + (kc + t4) * 4);
                a[mi][1] = *(uint32_t*)(Ac + (r + 8) * TFROW_A + (kc + t4) * 4);
                a[mi][2] = *(uint32_t*)(Ac + r * TFROW_A + (kc + t4 + 4) * 4);
                a[mi][3] = *(uint32_t*)(Ac + (r + 8) * TFROW_A + (kc + t4 + 4) * 4);
            }
            int bb = t4 * 32 + ks * 8;
#pragma unroll
            for (int ni = 0; ni < 8; ni++) {
                int rn = nbase + ni * 8 + g;
                uint2 pb = *(uint2*)(Bc + rn * TFROW_B + bb);
#pragma unroll
                for (int mi = 0; mi < 2; mi++)
                    MMA_TF32(acc[mi][ni], a[mi][0], a[mi][1], a[mi][2], a[mi][3], pb.x, pb.y);
            }
        }
        if (more) {
            tf_commitA<SILU>(nxt, tid, va, vu);
            tf_commitB(nxt + TFTILE_A, tid, vb);
        }
        __syncthreads();
    }

#pragma unroll
    for (int mi = 0; mi < 2; mi++)
#pragma unroll
        for (int ni = 0; ni < 8; ni++) {
            int gm = m0 + mbase + mi * 16 + g;
            int gn = n0 + nbase + ni * 8 + t4 * 2;
            const float* c = acc[mi][ni];
#pragma unroll
            for (int hrow = 0; hrow < 2; hrow++) {
                long long ci = (long long)(gm + hrow * 8) * ldc + gn;
#pragma unroll
                for (int j = 0; j < 2; j++) {
                    float v = c[hrow * 2 + j] * scale;
                    if (EPI == 1)      v += bias[gn + j];
                    else if (EPI == 2) v = 1.f / (1.f + expf(-(v + bias[gn + j])));
                    else if (EPI == 3) v += bias[gn + j] + Cm[ci + j];
                    Cm[ci + j] = v;
                }
            }
        }
}

// =====================================================================
//     attention scores: S = Q K^T / 8  (split-bf16, K=64, z = b*H+h)
// =====================================================================
__global__ void __launch_bounds__(256, 1) attn_sc_k(
    const float* __restrict__ qkv, const float* __restrict__ kf,
    float* __restrict__ sc)
{
    extern __shared__ char smem[];
    int z = blockIdx.z, b = z >> 4, h = z & 15;
    int m0 = blockIdx.y * 128, n0 = blockIdx.x * 128;
    const float* A  = qkv + (long long)b * C_ * 3072 + h * 64;
    const float* Bp = kf + (long long)b * PC_ * D_ + h * 64;
    int tid = threadIdx.x, wid = tid >> 5, lid = tid & 31;

#pragma unroll
    for (int kc = 0; kc < 2; kc++) {
        float4 va[4];
        issue_f32<0>(A, 3072, m0, kc * 32, tid, va);
        commit_f32<0>(smem + kc * 2 * TILE_B, smem + kc * 2 * TILE_B + TILE_B, tid, va);
        int r = tid >> 1, hh = tid & 1;
        int j = n0 + r;
        float4 vb[4];
        if (j < PC_) {
#pragma unroll
            for (int i = 0; i < 4; i++)
                vb[i] = *(const float4*)(Bp + (long long)j * D_ + kc * 32 + hh * 16 + i * 4);
        } else {
#pragma unroll
            for (int i = 0; i < 4; i++) vb[i] = make_float4(0.f, 0.f, 0.f, 0.f);
        }
        commit_f32<0>(smem + (4 + kc * 2) * TILE_B, smem + (4 + kc * 2) * TILE_B + TILE_B, tid, vb);
    }
    __syncthreads();

    int g = lid >> 2, t4 = lid & 3;
    int mbase = (wid & 3) * 32, nbase = (wid >> 2) * 64;
    float acc[2][8][4];
#pragma unroll
    for (int mi = 0; mi < 2; mi++)
#pragma unroll
        for (int ni = 0; ni < 8; ni++)
#pragma unroll
            for (int j = 0; j < 4; j++) acc[mi][ni][j] = 0.f;

#pragma unroll
    for (int kc = 0; kc < 2; kc++) {
        char* Ah = smem + kc * 2 * TILE_B;       char* Al = Ah + TILE_B;
        char* Bh = smem + (4 + kc * 2) * TILE_B; char* Bl = Bh + TILE_B;
#pragma unroll
        for (int k16 = 0; k16 < 2; k16++) {
            int kcc = k16 * 16;
            uint32_t ah[2][4], al[2][4];
#pragma unroll
            for (int mi = 0; mi < 2; mi++) {
                int r = mbase + mi * 16 + g;
                int c = kcc + t4 * 2;
                ah[mi][0] = *(uint32_t*)(Ah + r * 80 + c * 2);
                ah[mi][1] = *(uint32_t*)(Ah + (r + 8) * 80 + c * 2);
                ah[mi][2] = *(uint32_t*)(Ah + r * 80 + (c + 8) * 2);
                ah[mi][3] = *(uint32_t*)(Ah + (r + 8) * 80 + (c + 8) * 2);
                al[mi][0] = *(uint32_t*)(Al + r * 80 + c * 2);
                al[mi][1] = *(uint32_t*)(Al + (r + 8) * 80 + c * 2);
                al[mi][2] = *(uint32_t*)(Al + r * 80 + (c + 8) * 2);
                al[mi][3] = *(uint32_t*)(Al + (r + 8) * 80 + (c + 8) * 2);
            }
#pragma unroll
            for (int ni = 0; ni < 8; ni++) {
                int r = nbase + ni * 8 + g;
                int c = kcc + t4 * 2;
                uint32_t bh0 = *(uint32_t*)(Bh + r * 80 + c * 2);
                uint32_t bh1 = *(uint32_t*)(Bh + r * 80 + (c + 8) * 2);
                uint32_t bl0 = *(uint32_t*)(Bl + r * 80 + c * 2);
                uint32_t bl1 = *(uint32_t*)(Bl + r * 80 + (c + 8) * 2);
#pragma unroll
                for (int mi = 0; mi < 2; mi++) {
                    MMA_B16(acc[mi][ni], ah[mi][0], ah[mi][1], ah[mi][2], ah[mi][3], bh0, bh1);
                    MMA_B16(acc[mi][ni], ah[mi][0], ah[mi][1], ah[mi][2], ah[mi][3], bl0, bl1);
                    MMA_B16(acc[mi][ni], al[mi][0], al[mi][1], al[mi][2], al[mi][3], bh0, bh1);
                }
            }
        }
    }
#pragma unroll
    for (int mi = 0; mi < 2; mi++)
#pragma unroll
        for (int ni = 0; ni < 8; ni++) {
            int gm = m0 + mbase + mi * 16 + g;
            int gn = n0 + nbase + ni * 8 + t4 * 2;
            const float* c = acc[mi][ni];
#pragma unroll
            for (int hrow = 0; hrow < 2; hrow++) {
                long long ci = ((long long)z * C_ + gm + hrow * 8) * PCs + gn;
                sc[ci]     = c[hrow * 2 + 0] * 0.125f;
                sc[ci + 1] = c[hrow * 2 + 1] * 0.125f;
            }
        }
}

// =====================================================================
//     attention P@V: ao[s][h*64+d] = sum_j P[s][j] V[j][d]   (K=544)
// =====================================================================
__global__ void __launch_bounds__(256) attn_pv_k(
    const float* __restrict__ sc, const float* __restrict__ vf,
    float* __restrict__ ao)
{
    __shared__ char sP[2 * TILE_B];
    __shared__ char sV[2 * 5120];
    int z = blockIdx.y, b = z >> 4, h = z & 15;
    int m0 = blockIdx.x * 128;
    const float* P = sc + ((long long)z * C_ + m0) * PCs;
    const float* V = vf + (long long)b * PC_ * D_ + h * 64;
    int tid = threadIdx.x, wid = tid >> 5, lid = tid & 31;
    int g = lid >> 2, t4 = lid & 3;

    float acc[8][4];
#pragma unroll
    for (int ni = 0; ni < 8; ni++)
#pragma unroll
        for (int j = 0; j < 4; j++) acc[ni][j] = 0.f;

    for (int kt = 0; kt < 17; kt++) {
        int k0 = kt * 32;
        float4 vp[4];
        issue_f32<0>(P, PCs, 0, k0, tid, vp);
        int jj = tid >> 3, d0 = (tid & 7) * 8;
        int j = k0 + jj;
        float4 v0 = make_float4(0.f, 0.f, 0.f, 0.f), v1 = v0;
        if (j < PC_) {
            v0 = *(const float4*)(V + (long long)j * D_ + d0);
            v1 = *(const float4*)(V + (long long)j * D_ + d0 + 4);
        }
        __syncthreads();
        commit_f32<0>(sP, sP + TILE_B, tid, vp);
        {
            float xs[8] = {v0.x, v0.y, v0.z, v0.w, v1.x, v1.y, v1.z, v1.w};
#pragma unroll
            for (int e = 0; e < 8; e++) {
                int d = d0 + e;
                __nv_bfloat16 hh, ll;
                cvt2(xs[e], hh, ll);
                *(__nv_bfloat16*)(sV + d * 80 + jj * 2) = hh;
                *(__nv_bfloat16*)(sV + 5120 + d * 80 + jj * 2) = ll;
            }
        }
        __syncthreads();
#pragma unroll
        for (int k16 = 0; k16 < 2; k16++) {
            int c = k16 * 16 + t4 * 2;
            int r = wid * 16 + g;
            uint32_t ph[4], pl[4];
            ph[0] = *(uint32_t*)(sP + r * 80 + c * 2);
            ph[1] = *(uint32_t*)(sP + (r + 8) * 80 + c * 2);
            ph[2] = *(uint32_t*)(sP + r * 80 + (c + 8) * 2);
            ph[3] = *(uint32_t*)(sP + (r + 8) * 80 + (c + 8) * 2);
            pl[0] = *(uint32_t*)(sP + TILE_B + r * 80 + c * 2);
            pl[1] = *(uint32_t*)(sP + TILE_B + (r + 8) * 80 + c * 2);
            pl[2] = *(uint32_t*)(sP + TILE_B + r * 80 + (c + 8) * 2);
            pl[3] = *(uint32_t*)(sP + TILE_B + (r + 8) * 80 + (c + 8) * 2);
#pragma unroll
            for (int ni = 0; ni < 8; ni++) {
                int d = ni * 8 + g;
                uint32_t bh0 = *(uint32_t*)(sV + d * 80 + c * 2);
                uint32_t bh1 = *(uint32_t*)(sV + d * 80 + (c + 8) * 2);
                uint32_t bl0 = *(uint32_t*)(sV + 5120 + d * 80 + c * 2);
                uint32_t bl1 = *(uint32_t*)(sV + 5120 + d * 80 + (c + 8) * 2);
                MMA_B16(acc[ni], ph[0], ph[1], ph[2], ph[3], bh0, bh1);
                MMA_B16(acc[ni], ph[0], ph[1], ph[2], ph[3], bl0, bl1);
                MMA_B16(acc[ni], pl[0], pl[1], pl[2], pl[3], bh0, bh1);
            }
        }
    }
#pragma unroll
    for (int ni = 0; ni < 8; ni++) {
        int gm = m0 + wid * 16 + g;
        int gn = ni * 8 + t4 * 2;
        float* o = ao + ((long long)b * C_ + gm) * D_ + h * 64 + gn;
        o[0] = acc[ni][0]; o[1] = acc[ni][1];
        float* o2 = o + 8 * D_;
        o2[0] = acc[ni][2]; o2[1] = acc[ni][3];
    }
}

// ---------------- block reductions ----------------
__device__ __forceinline__ float blockReduceSum(float v) {
    __shared__ float sh[33];
    int lane = threadIdx.x & 31, w = threadIdx.x >> 5, nw = blockDim.x >> 5;
#pragma unroll
    for (int o = 16; o; o >>= 1) v += __shfl_xor_sync(0xffffffffu, v, o);
    __syncthreads();
    if (lane == 0) sh[w] = v;
    __syncthreads();
    if (w == 0) {
        float t = (lane < nw) ? sh[lane] : 0.f;
#pragma unroll
        for (int o = 16; o; o >>= 1) t += __shfl_xor_sync(0xffffffffu, t, o);
        if (lane == 0) sh[32] = t;
    }
    __syncthreads();
    return sh[32];
}

// ---------------- layernorm ----------------
__global__ void ln_kernel(const float* __restrict__ xin, int gather, int c0,
                          const float* __restrict__ add,
                          const float* __restrict__ gamma, const float* __restrict__ beta,
                          float* __restrict__ out)
{
    int t = blockIdx.x;
    const float* px;
    if (gather) {
        int b = t >> 9, s = t & 511;
        px = xin + ((size_t)b * S_ + c0 + s) * D_;
    } else {
        px = xin + (size_t)t * D_;
    }
    int i0 = threadIdx.x * 4;
    float4 v = *(const float4*)(px + i0);
    if (add) {
        float4 a = *(const float4*)(add + (size_t)t * D_ + i0);
        v.x += a.x; v.y += a.y; v.z += a.z; v.w += a.w;
    }
    float mean = blockReduceSum(v.x + v.y + v.z + v.w) * (1.f / D_);
    float dx = v.x - mean, dy = v.y - mean, dz = v.z - mean, dw = v.w - mean;
    float var = blockReduceSum(dx*dx + dy*dy + dz*dz + dw*dw) * (1.f / D_);
    float inv = rsqrtf(var + 1e-5f);
    float4 gv = *(const float4*)(gamma + i0);
    float4 bv = *(const float4*)(beta + i0);
    float4 o;
    o.x = dx * inv * gv.x + bv.x;
    o.y = dy * inv * gv.y + bv.y;
    o.z = dz * inv * gv.z + bv.z;
    o.w = dw * inv * gv.w + bv.w;
    *(float4*)(out + (size_t)t * D_ + i0) = o;
}

__global__ void rownorm_kernel(float* __restrict__ a, int ld, int off) {
    int t = blockIdx.x;
    float* p = a + (size_t)t * ld + off;
    int i0 = threadIdx.x * 4;
    float4 v = *(const float4*)(p + i0);
    float ss = blockReduceSum(v.x*v.x + v.y*v.y + v.z*v.z + v.w*v.w);
    float inv = rsqrtf(ss + 1e-6f);
    v.x *= inv; v.y *= inv; v.z *= inv; v.w *= inv;
    *(float4*)(p + i0) = v;
}

// warp-per-row softmax: block=256 handles 8 rows
__global__ void softmax_kernel(float* __restrict__ sc) {
    int row = blockIdx.x * 8 + (threadIdx.x >> 5);
    int lane = threadIdx.x & 31;
    int i = row & (C_ - 1);
    int valid = P_ + i + 1;
    float* r = sc + (size_t)row * PCs;
    float mx = -1e30f;
    for (int j = lane; j < valid; j += 32) mx = fmaxf(mx, r[j]);
#pragma unroll
    for (int o = 16; o; o >>= 1) mx = fmaxf(mx, __shfl_xor_sync(0xffffffffu, mx, o));
    float s = 0.f;
    for (int j = lane; j < valid; j += 32) { float e = expf(r[j] - mx); r[j] = e; s += e; }
#pragma unroll
    for (int o = 16; o; o >>= 1) s += __shfl_xor_sync(0xffffffffu, s, o);
    float inv = 1.f / s;
    for (int j = lane; j < PCs; j += 32) r[j] = (j < valid) ? r[j] * inv : 0.f;
}

__global__ void pack_kernel(const float* __restrict__ pk, const float* __restrict__ pv,
                            const float* __restrict__ qkv,
                            float* __restrict__ kf, float* __restrict__ vf)
{
    int bj = blockIdx.x;
    int b = bj / PC_, j = bj - b * PC_;
    size_t dst = (size_t)bj * D_ + threadIdx.x * 4;
    float4 kq, vq;
    if (j < P_) {
        kq = *(const float4*)(pk + (size_t)j * D_ + threadIdx.x * 4);
        vq = *(const float4*)(pv + (size_t)j * D_ + threadIdx.x * 4);
    } else {
        size_t row = ((size_t)b * C_ + (j - P_)) * 3072;
        kq = *(const float4*)(qkv + row + 1024 + threadIdx.x * 4);
        vq = *(const float4*)(qkv + row + 2048 + threadIdx.x * 4);
    }
    *(float4*)(kf + dst) = kq;
    *(float4*)(vf + dst) = vq;
}

__global__ void zero2_kernel(float4* a, float4* b, int n4) {
    int i = blockIdx.x * blockDim.x + threadIdx.x;
    float4 z = make_float4(0.f, 0.f, 0.f, 0.f);
    if (i < n4) { a[i] = z; b[i] = z; }
}
__global__ void update_kernel(float4* __restrict__ M, float4* __restrict__ St,
                              const float4* __restrict__ grad,
                              const float* lr, const float* mom, const float* fg, int n4) {
    float theta = 1.f / (1.f + expf(-lr[0]));
    float eta   = 1.f / (1.f + expf(-mom[0]));
    float alpha = 1.f / (1.f + expf(-fg[0]));
    int i = blockIdx.x * blockDim.x + threadIdx.x;
    if (i < n4) {
        float4 st = St[i], gr = grad[i], m = M[i];
        st.x = eta * st.x - theta * gr.x;
        st.y = eta * st.y - theta * gr.y;
        st.z = eta * st.z - theta * gr.z;
        st.w = eta * st.w - theta * gr.w;
        St[i] = st;
        m.x = (1.f - alpha) * m.x + st.x;
        m.y = (1.f - alpha) * m.y + st.y;
        m.z = (1.f - alpha) * m.z + st.z;
        m.w = (1.f - alpha) * m.w + st.w;
        M[i] = m;
    }
}
__global__ void combine_kernel(const float* __restrict__ x, const float4* __restrict__ gt,
                               const float4* __restrict__ ap, const float4* __restrict__ mem,
                               float* __restrict__ out, int c0) {
    int i = blockIdx.x * blockDim.x + threadIdx.x;
    int t = i >> 8, d = (i & 255) * 4;
    int b = t >> 9, s = t & 511;
    size_t xi = ((size_t)b * S_ + c0 + s) * D_ + d;
    float4 xv = *(const float4*)(x + xi);
    float4 g = gt[i], a = ap[i], m = mem[i];
    float4 o;
    o.x = xv.x + g.x * a.x + (1.f - g.x) * m.x;
    o.y = xv.y + g.y * a.y + (1.f - g.y) * m.y;
    o.z = xv.z + g.z * a.z + (1.f - g.z) * m.z;
    o.w = xv.w + g.w * a.w + (1.f - g.w) * m.w;
    *(float4*)(out + xi) = o;
}

// ---------------- host side ----------------
static float* symaddr(const void* s) {
    void* p = nullptr;
    cudaGetSymbolAddress(&p, s);
    return (float*)p;
}

template<int TRA, int TRB, int EPI>
static void mm(const float* A, const float* Bf, const float* bias, float* Cm,
               int M, int N, int K, long long lda, long long ldb, long long ldc,
               float scale, int Z, int zdiv,
               long long aO, long long aI, long long bO, long long bI,
               long long cO, long long cI)
{
    cudaFuncSetAttribute(mm_k<TRA, TRB, EPI>,
                         cudaFuncAttributeMaxDynamicSharedMemorySize, SMEM_MM);
    dim3 grid(N / 128, M / 128, Z);
    mm_k<TRA, TRB, EPI><<<grid, 256, SMEM_MM>>>(
        A, Bf, bias, Cm, M, N, K, lda, ldb, ldc, scale, zdiv,
        aO, aI, bO, bI, cO, cI);
}

template<int EPI, int SILU>
static void mmtf(const float* A, const uint32_t* W, const float* bias, float* Cm,
                 int M, int N, int K, long long lda, long long ldc, float scale,
                 int Z, long long aO, long long cO)
{
    cudaFuncSetAttribute(mmtf_k<EPI, SILU>,
                         cudaFuncAttributeMaxDynamicSharedMemorySize, SMEM_TF);
    dim3 grid(N / 128, M / 128, Z);
    mmtf_k<EPI, SILU><<<grid, 256, SMEM_TF>>>(A, W, bias, Cm, M, N, K, lda, ldc,
                                              scale, aO, cO);
}

extern "C" void kernel_launch(void* const* d_in, const int* in_sizes, int n_in,
                              void* d_out, int out_size)
{
    const float* x     = (const float*)d_in[0];
    const float* g1    = (const float*)d_in[1];
    const float* b1    = (const float*)d_in[2];
    const float* g2    = (const float*)d_in[3];
    const float* b2p   = (const float*)d_in[4];
    const float* g3    = (const float*)d_in[5];
    const float* b3    = (const float*)d_in[6];
    const float* Wqm   = (const float*)d_in[7];
    const float* Wkm   = (const float*)d_in[8];
    const float* Wvm   = (const float*)d_in[9];
    const float* lr    = (const float*)d_in[10];
    const float* mom   = (const float*)d_in[11];
    const float* fg    = (const float*)d_in[12];
    const float* Wq    = (const float*)d_in[13];
    const float* bq    = (const float*)d_in[14];
    const float* Wk    = (const float*)d_in[15];
    const float* bk    = (const float*)d_in[16];
    const float* Wv    = (const float*)d_in[17];
    const float* bv    = (const float*)d_in[18];
    const float* Wo    = (const float*)d_in[19];
    const float* bo    = (const float*)d_in[20];
    const float* pk    = (const float*)d_in[21];
    const float* pv    = (const float*)d_in[22];
    const float* Wg    = (const float*)d_in[23];
    const float* bg    = (const float*)d_in[24];
    const float* Wgate = (const float*)d_in[25];
    const float* bgate = (const float*)d_in[26];
    const float* Wup   = (const float*)d_in[27];
    const float* bup   = (const float*)d_in[28];
    const float* Wdown = (const float*)d_in[29];
    const float* bdown = (const float*)d_in[30];
    float* out = (float*)d_out;

    float* pM   = symaddr(g_M);
    float* pSt  = symaddr(g_St);
    float* pGr  = symaddr(g_grad);
    float* ph1  = symaddr(g_h1);
    float* pmm3 = symaddr(g_mm3);
    float* pmp  = symaddr(g_mp);
    float* pmem = pmp;
    float* ppr  = pmp + (size_t)NTOK * D_;
    float* ph2  = symaddr(g_h2);
    float* pqkv = symaddr(g_qkv);
    float* pkf  = symaddr(g_kf);
    float* pvf  = symaddr(g_vf);
    float* psc  = symaddr(g_sc);
    float* pao  = symaddr(g_ao);
    float* pap  = symaddr(g_ap);
    float* pgt  = symaddr(g_gt);
    float* ph3  = symaddr(g_h3);
    float* pff  = symaddr(g_ff);
    float* pb3  = symaddr(g_bias3);
    float* pbff = symaddr(g_biasff);
    uint32_t* wt = (uint32_t*)symaddr(g_wt);

    const long long oWqm = 0, oWq = 3145728,
                    oWo = 6291456, oWg = 7340032,
                    oWgate = 8388608, oWdown = 16777216;

    dim3 blk(32, 8);
    wtf32_k<<<dim3(D_/32, D_/32), blk>>>(Wqm, wt + oWqm,           D_, D_);
    wtf32_k<<<dim3(D_/32, D_/32), blk>>>(Wkm, wt + oWqm + 1048576, D_, D_);
    wtf32_k<<<dim3(D_/32, D_/32), blk>>>(Wvm, wt + oWqm + 2097152, D_, D_);

    const int BDD = B_ * D_ * D_;
    zero2_kernel<<<(BDD/4 + 255) / 256, 256>>>((float4*)pM, (float4*)pSt, BDD/4);

    const long long CD  = (long long)C_ * D_;
    const long long DD  = (long long)D_ * D_;

    cudaFuncSetAttribute(attn_sc_k, cudaFuncAttributeMaxDynamicSharedMemorySize, SMEM_MM);

    for (int c = 0; c < NCH; c++) {
        int c0 = c * C_;

        ln_kernel<<<NTOK, 256>>>(x, 1, c0, nullptr, g1, b1, ph1);

        // merged neural-memory projections (tf32)
        mmtf<0,0>(ph1, wt + oWqm, nullptr, pmm3, NTOK, 3072, D_, D_, 3072, 1.f, 1, 0, 0);

        if (c == 0) {
            wtf32_k<<<dim3(D_/32, D_/32),  blk>>>(Wq,    wt + oWq,              D_, D_);
            wtf32_k<<<dim3(D_/32, D_/32),  blk>>>(Wk,    wt + oWq + 1048576,    D_, D_);
            wtf32_k<<<dim3(D_/32, D_/32),  blk>>>(Wv,    wt + oWq + 2097152,    D_, D_);
            wtf32_k<<<dim3(D_/32, D_/32),  blk>>>(Wo,    wt + oWo,              D_, D_);
            wtf32_k<<<dim3(D_/32, D_/32),  blk>>>(Wg,    wt + oWg,              D_, D_);
            wtf32_k<<<dim3(FF_/32, D_/32), blk>>>(Wgate, wt + oWgate,           D_, FF_);
            wtf32_k<<<dim3(FF_/32, D_/32), blk>>>(Wup,   wt + oWgate + 4194304, D_, FF_);
            wtf32_k<<<dim3(D_/32, FF_/32), blk>>>(Wdown, wt + oWdown,           FF_, D_);
            cat3_k<<<12, 256>>>(bq, bk, bv, pb3);
            cat2_k<<<32, 256>>>(bgate, bup, pbff);
        }

        rownorm_kernel<<<NTOK, 256>>>(pmm3, 3072, 1024);

        // mem/pred (bf16 split); pred half gets vm subtracted in epilogue (EPI=4)
        mm<0,0,4>(pmm3, pM, pmm3 + 2048, pmp, C_, D_, D_,
                  3072, D_, D_, 1.f, 8, 4,
                  1024, (long long)C_ * 3072, 0, DD,
                  (long long)NTOK * D_, CD);

        mm<1,1,0>(ppr, pmm3 + 1024, nullptr, pGr, D_, D_, C_,
                  D_, 3072, D_, 1.f / C_, B_, 1,
                  CD, 0, (long long)C_ * 3072, 0, DD, 0);

        update_kernel<<<(BDD/4 + 255) / 256, 256>>>((float4*)pM, (float4*)pSt,
                                                    (const float4*)pGr, lr, mom, fg, BDD/4);

        ln_kernel<<<NTOK, 256>>>(x, 1, c0, pmem, g2, b2p, ph2);

        // merged q,k,v (tf32)
        mmtf<1,0>(ph2, wt + oWq, pb3, pqkv, NTOK, 3072, D_, D_, 3072, 1.f, 1, 0, 0);

        pack_kernel<<<B_ * PC_, 256>>>(pk, pv, pqkv, pkf, pvf);

        attn_sc_k<<<dim3(5, 4, B_ * H_), 256, SMEM_MM>>>(pqkv, pkf, psc);
        softmax_kernel<<<B_ * H_ * C_ / 8, 256>>>(psc);
        attn_pv_k<<<dim3(4, B_ * H_), 256>>>(psc, pvf, pao);

        mmtf<1,0>(pao,  wt + oWo, bo, pap, NTOK, D_, D_, D_, D_, 1.f, 1, 0, 0);
        mmtf<2,0>(pmem, wt + oWg, bg, pgt, NTOK, D_, D_, D_, D_, 1.f, 1, 0, 0);

        combine_kernel<<<(NTOK * D_ / 4 + 255) / 256, 256>>>(x, (const float4*)pgt,
                                                             (const float4*)pap,
                                                             (const float4*)pmem, out, c0);

        ln_kernel<<<NTOK, 256>>>(out, 1, c0, nullptr, g3, b3, ph3);
        mmtf<1,0>(ph3, wt + oWgate, pbff, pff, NTOK, 8192, D_, D_, 8192, 1.f, 1, 0, 0);
        // down proj: A = silu(gate)*up computed in the loader (no silu kernel)
        mmtf<3,1>(pff, wt + oWdown, bdown, out + (size_t)c0 * D_,
                  C_, D_, FF_, 8192, D_, 1.f, B_,
                  (long long)C_ * 8192, (long long)S_ * D_);
    }
}

// round 16
// speedup vs baseline: 1.2127x; 1.0905x over previous
#include <cuda_runtime.h>
#include <cuda_bf16.h>
#include <math.h>
#include <stdint.h>

// ---------------- problem constants ----------------
#define B_   4
#define S_   4096
#define D_   1024
#define H_   16
#define DH_  64
#define P_   16
#define C_   512
#define FF_  4096
#define NTOK 2048      /* B_*C_ tokens per chunk */
#define PC_  528       /* P_ + C_ */
#define PCs  640       /* padded score stride */
#define NCH  8         /* S_/C_ chunks */

// ---------------- device scratch (no allocation allowed) ----------------
__device__ float g_M   [(size_t)B_*D_*D_];      // TRANSPOSED: Mt[v][k] = M[k][v]
__device__ float g_St  [(size_t)B_*D_*D_];
__device__ float g_grad[(size_t)B_*D_*D_];
__device__ float g_h1  [(size_t)NTOK*D_];
__device__ float g_mm3 [(size_t)NTOK*3072];     // [qm|km|vm] ld=3072
__device__ float g_mp  [(size_t)2*NTOK*D_];     // [mem_ctx ; pred-vm] contiguous
__device__ float g_h2  [(size_t)NTOK*D_];
__device__ float g_qkv [(size_t)NTOK*3072];     // [qh|kh|vh] ld=3072
__device__ float g_kf  [(size_t)B_*PC_*D_];
__device__ float g_vf  [(size_t)B_*PC_*D_];
__device__ float g_sc  [(size_t)B_*H_*C_*PCs];
__device__ float g_ao  [(size_t)NTOK*D_];
__device__ float g_ap  [(size_t)NTOK*D_];
__device__ float g_gt  [(size_t)NTOK*D_];
__device__ float g_h3  [(size_t)NTOK*D_];
__device__ float g_ff  [(size_t)NTOK*8192];     // [gate|up] ld=8192
__device__ float g_bias3 [3072];
__device__ float g_biasff[8192];
// pre-transposed weights [N,K] in tf32 (u32), k pair-permuted per 32-chunk
#define WTOT 20971520
__device__ uint32_t g_wt[WTOT];

__device__ __forceinline__ void cvt2(float x, __nv_bfloat16& h, __nv_bfloat16& l) {
    h = __float2bfloat16(x);
    l = __float2bfloat16(x - __bfloat162float(h));
}
__device__ __forceinline__ uint32_t f2tf(float x) {
    uint32_t r; asm("cvt.rna.tf32.f32 %0, %1;" : "=r"(r) : "f"(x)); return r;
}

// =====================================================================
//   weight transpose+tf32:  src[K,N] fp32 -> dst[N,K] tf32,
//   k pair-permuted within 32-word chunks
// =====================================================================
__global__ void wtf32_k(const float* __restrict__ src, uint32_t* __restrict__ dst,
                        int K, int N)
{
    __shared__ float t[32][33];
    int nb = blockIdx.x * 32, kb = blockIdx.y * 32;
    int tx = threadIdx.x, ty = threadIdx.y;
#pragma unroll
    for (int i = 0; i < 32; i += 8)
        t[ty + i][tx] = src[(long long)(kb + ty + i) * N + nb + tx];
    __syncthreads();
    int ks = tx >> 3, rem = tx & 7;
    int s_local = (rem & 3) * 8 + ks * 2 + (rem >> 2);
#pragma unroll
    for (int i = 0; i < 32; i += 8) {
        long long o = (long long)(nb + ty + i) * K + kb + s_local;
        dst[o] = f2tf(t[tx][ty + i]);
    }
}

__global__ void cat3_k(const float* a, const float* b, const float* c, float* d) {
    int i = blockIdx.x * 256 + threadIdx.x;
    d[i] = (i < 1024) ? a[i] : (i < 2048) ? b[i - 1024] : c[i - 2048];
}
__global__ void cat2_k(const float* a, const float* b, float* d) {
    int i = blockIdx.x * 256 + threadIdx.x;
    d[i] = (i < 4096) ? a[i] : b[i - 4096];
}

// =====================================================================
//      bf16 split GEMM (state GEMMs): block 128x128x32, 8 warps
// =====================================================================
#define TILE_B 10240              /* 128 rows x 80 bytes */
#define SMEM_MM (8*TILE_B)        /* 81920 */

#define MMA_B16(c, a0, a1, a2, a3, b0, b1)                                     \
    asm volatile("mma.sync.aligned.m16n8k16.row.col.f32.bf16.bf16.f32 "        \
                 "{%0,%1,%2,%3}, {%4,%5,%6,%7}, {%8,%9}, {%0,%1,%2,%3};"       \
                 : "+f"(c[0]), "+f"(c[1]), "+f"(c[2]), "+f"(c[3])              \
                 : "r"(a0), "r"(a1), "r"(a2), "r"(a3), "r"(b0), "r"(b1))

#define MMA_TF32(c, a0, a1, a2, a3, b0, b1)                                    \
    asm volatile("mma.sync.aligned.m16n8k8.row.col.f32.tf32.tf32.f32 "         \
                 "{%0,%1,%2,%3}, {%4,%5,%6,%7}, {%8,%9}, {%0,%1,%2,%3};"       \
                 : "+f"(c[0]), "+f"(c[1]), "+f"(c[2]), "+f"(c[3])              \
                 : "r"(a0), "r"(a1), "r"(a2), "r"(a3), "r"(b0), "r"(b1))

// ---- fp32 loaders (bf16 hi/lo commit) ----
template<int TR>
__device__ __forceinline__ void issue_f32(const float* __restrict__ src, long long ld,
                                          int row0, int k0, int tid, float4 v[4]) {
    if (TR == 0) {
        int r = tid >> 1, h = tid & 1;
#pragma unroll
        for (int i = 0; i < 4; i++)
            v[i] = *(const float4*)(src + (long long)(row0 + r) * ld + k0 + h * 16 + i * 4);
    } else {
        int kk = tid >> 3, q = tid & 7;
#pragma unroll
        for (int i = 0; i < 4; i++)
            v[i] = *(const float4*)(src + (long long)(k0 + kk) * ld + row0 + (q + i * 8) * 4);
    }
}
template<int TR>
__device__ __forceinline__ void commit_f32(char* dhi, char* dlo, int tid, const float4 v[4]) {
    if (TR == 0) {
        int r = tid >> 1, h = tid & 1;
#pragma unroll
        for (int i = 0; i < 4; i++) {
            int c = h * 16 + i * 4;
            __nv_bfloat16 h0, h1, h2, h3, l0, l1, l2, l3;
            cvt2(v[i].x, h0, l0); cvt2(v[i].y, h1, l1);
            cvt2(v[i].z, h2, l2); cvt2(v[i].w, h3, l3);
            uint2 hp, lp;
            hp.x = (uint32_t)__bfloat16_as_ushort(h0) | ((uint32_t)__bfloat16_as_ushort(h1) << 16);
            hp.y = (uint32_t)__bfloat16_as_ushort(h2) | ((uint32_t)__bfloat16_as_ushort(h3) << 16);
            lp.x = (uint32_t)__bfloat16_as_ushort(l0) | ((uint32_t)__bfloat16_as_ushort(l1) << 16);
            lp.y = (uint32_t)__bfloat16_as_ushort(l2) | ((uint32_t)__bfloat16_as_ushort(l3) << 16);
            *(uint2*)(dhi + r * 80 + c * 2) = hp;
            *(uint2*)(dlo + r * 80 + c * 2) = lp;
        }
    } else {
        int kk = tid >> 3, q = tid & 7;
#pragma unroll
        for (int i = 0; i < 4; i++) {
            int m = (q + i * 8) * 4;
            float xs[4] = {v[i].x, v[i].y, v[i].z, v[i].w};
#pragma unroll
            for (int j = 0; j < 4; j++) {
                __nv_bfloat16 h, l;
                cvt2(xs[j], h, l);
                *(__nv_bfloat16*)(dhi + (m + j) * 80 + kk * 2) = h;
                *(__nv_bfloat16*)(dlo + (m + j) * 80 + kk * 2) = l;
            }
        }
    }
}

// EPI: 0=store 1=+bias 2=sigmoid(+bias) 3=accum(+bias) 4=store, pred-half minus vm
template<int TRA, int TRB, int EPI>
__global__ void __launch_bounds__(256, 1) mm_k(
    const float* __restrict__ A, const float* __restrict__ Bf,
    const float* __restrict__ bias, float* __restrict__ Cm,
    int M, int N, int K, long long lda, long long ldb, long long ldc, float scale,
    int zdiv,
    long long aO, long long aI, long long bO, long long bI, long long cO, long long cI)
{
    extern __shared__ char smem[];
    int z = blockIdx.z;
    int zq = z / zdiv, zr = z % zdiv;
    A  += zq * aO + zr * aI;
    Bf += zq * bO + zr * bI;
    Cm += zq * cO + zr * cI;

    int tid = threadIdx.x, wid = tid >> 5, lid = tid & 31;
    int m0 = blockIdx.y * 128, n0 = blockIdx.x * 128;

    float acc[2][8][4];
#pragma unroll
    for (int mi = 0; mi < 2; mi++)
#pragma unroll
        for (int ni = 0; ni < 8; ni++)
#pragma unroll
            for (int j = 0; j < 4; j++) acc[mi][ni][j] = 0.f;

    {
        float4 va[4], vb[4];
        issue_f32<TRA>(A, lda, m0, 0, tid, va);
        commit_f32<TRA>(smem, smem + TILE_B, tid, va);
        issue_f32<TRB>(Bf, ldb, n0, 0, tid, vb);
        commit_f32<TRB>(smem + 2 * TILE_B, smem + 3 * TILE_B, tid, vb);
    }
    __syncthreads();

    int g = lid >> 2, t4 = lid & 3;
    int mbase = (wid & 3) * 32, nbase = (wid >> 2) * 64;
    int KT = K / 32;

    for (int kt = 0; kt < KT; kt++) {
        char* cur = smem + (kt & 1) * 4 * TILE_B;
        char* nxt = smem + ((kt + 1) & 1) * 4 * TILE_B;
        float4 va[4], vb[4];
        bool more = (kt + 1 < KT);
        if (more) {
            issue_f32<TRA>(A, lda, m0, (kt + 1) * 32, tid, va);
            issue_f32<TRB>(Bf, ldb, n0, (kt + 1) * 32, tid, vb);
        }
        char* Ah = cur;              char* Al = cur + TILE_B;
        char* Bh = cur + 2 * TILE_B; char* Bl = cur + 3 * TILE_B;
#pragma unroll
        for (int k16 = 0; k16 < 2; k16++) {
            int kc = k16 * 16;
            uint32_t ah[2][4], al[2][4];
#pragma unroll
            for (int mi = 0; mi < 2; mi++) {
                int r = mbase + mi * 16 + g;
                int c = kc + t4 * 2;
                ah[mi][0] = *(uint32_t*)(Ah + r * 80 + c * 2);
                ah[mi][1] = *(uint32_t*)(Ah + (r + 8) * 80 + c * 2);
                ah[mi][2] = *(uint32_t*)(Ah + r * 80 + (c + 8) * 2);
                ah[mi][3] = *(uint32_t*)(Ah + (r + 8) * 80 + (c + 8) * 2);
                al[mi][0] = *(uint32_t*)(Al + r * 80 + c * 2);
                al[mi][1] = *(uint32_t*)(Al + (r + 8) * 80 + c * 2);
                al[mi][2] = *(uint32_t*)(Al + r * 80 + (c + 8) * 2);
                al[mi][3] = *(uint32_t*)(Al + (r + 8) * 80 + (c + 8) * 2);
            }
#pragma unroll
            for (int ni = 0; ni < 8; ni++) {
                int r = nbase + ni * 8 + g;
                int c = kc + t4 * 2;
                uint32_t bh0 = *(uint32_t*)(Bh + r * 80 + c * 2);
                uint32_t bh1 = *(uint32_t*)(Bh + r * 80 + (c + 8) * 2);
                uint32_t bl0 = *(uint32_t*)(Bl + r * 80 + c * 2);
                uint32_t bl1 = *(uint32_t*)(Bl + r * 80 + (c + 8) * 2);
#pragma unroll
                for (int mi = 0; mi < 2; mi++) {
                    MMA_B16(acc[mi][ni], ah[mi][0], ah[mi][1], ah[mi][2], ah[mi][3], bh0, bh1);
                    MMA_B16(acc[mi][ni], ah[mi][0], ah[mi][1], ah[mi][2], ah[mi][3], bl0, bl1);
                    MMA_B16(acc[mi][ni], al[mi][0], al[mi][1], al[mi][2], al[mi][3], bh0, bh1);
                }
            }
        }
        if (more) {
            commit_f32<TRA>(nxt, nxt + TILE_B, tid, va);
            commit_f32<TRB>(nxt + 2 * TILE_B, nxt + 3 * TILE_B, tid, vb);
        }
        __syncthreads();
    }

#pragma unroll
    for (int mi = 0; mi < 2; mi++)
#pragma unroll
        for (int ni = 0; ni < 8; ni++) {
            int gm = m0 + mbase + mi * 16 + g;
            int gn = n0 + nbase + ni * 8 + t4 * 2;
            const float* c = acc[mi][ni];
#pragma unroll
            for (int hrow = 0; hrow < 2; hrow++) {
                long long ci = (long long)(gm + hrow * 8) * ldc + gn;
#pragma unroll
                for (int j = 0; j < 2; j++) {
                    float v = c[hrow * 2 + j] * scale;
                    if (EPI == 1)      v += bias[gn + j];
                    else if (EPI == 2) v = 1.f / (1.f + expf(-(v + bias[gn + j])));
                    else if (EPI == 3) v += bias[gn + j] + Cm[ci + j];
                    else if (EPI == 4) {
                        if (zq == 1)   // pred half: subtract vm (bias = pmm3+2048 view)
                            v -= bias[((long long)zr * C_ + gm + hrow * 8) * 3072 + gn + j];
                    }
                    Cm[ci + j] = v;
                }
            }
        }
}

// =====================================================================
//      TF32 single-pass weight GEMM (R12 config): block 128x128x32
//      A: linear layout, stride 144.  B: pair-permuted, stride 136.
// =====================================================================
#define TFROW_A 144
#define TFROW_B 136
#define TFTILE_A (128*TFROW_A)
#define TFTILE_B (128*TFROW_B)
#define TFSTAGE  (TFTILE_A+TFTILE_B)
#define SMEM_TF  (2*TFSTAGE)

__device__ __forceinline__ void tf_issueA(const float* __restrict__ src, long long ld,
                                          int row0, int k0, int tid, float4 v[4]) {
    int r = tid >> 1, h = tid & 1;
#pragma unroll
    for (int i = 0; i < 4; i++)
        v[i] = *(const float4*)(src + (long long)(row0 + r) * ld + k0 + h * 16 + i * 4);
}
__device__ __forceinline__ void tf_commitA(char* d, int tid, const float4 v[4]) {
    int r = tid >> 1, h = tid & 1;
#pragma unroll
    for (int i = 0; i < 4; i++) {
        uint4 u;
        u.x = f2tf(v[i].x); u.y = f2tf(v[i].y); u.z = f2tf(v[i].z); u.w = f2tf(v[i].w);
        *(uint4*)(d + r * TFROW_A + (h * 16 + i * 4) * 4) = u;
    }
}
__device__ __forceinline__ void tf_issueB(const uint32_t* __restrict__ src, long long K,
                                          int n0, int k0, int tid, uint4 v[4]) {
    int r = tid >> 1, h = tid & 1;
#pragma unroll
    for (int i = 0; i < 4; i++)
        v[i] = *(const uint4*)(src + (long long)(n0 + r) * K + k0 + h * 16 + i * 4);
}
// 8B stores only (TFROW_B=136 not 16B-aligned for odd rows)
__device__ __forceinline__ void tf_commitB(char* d, int tid, const uint4 v[4]) {
    int r = tid >> 1, h = tid & 1;
    char* base = d + r * TFROW_B + h * 64;
#pragma unroll
    for (int i = 0; i < 4; i++) {
        *(uint2*)(base + i * 16)     = make_uint2(v[i].x, v[i].y);
        *(uint2*)(base + i * 16 + 8) = make_uint2(v[i].z, v[i].w);
    }
}

template<int EPI>
__global__ void __launch_bounds__(256, 1) mmtf_k(
    const float* __restrict__ A, const uint32_t* __restrict__ W,
    const float* __restrict__ bias, float* __restrict__ Cm,
    int M, int N, int K, long long lda, long long ldc, float scale,
    long long aO, long long cO)
{
    extern __shared__ char smem[];
    int z = blockIdx.z;
    A  += (long long)z * aO;
    Cm += (long long)z * cO;

    int tid = threadIdx.x, wid = tid >> 5, lid = tid & 31;
    int m0 = blockIdx.y * 128, n0 = blockIdx.x * 128;

    float acc[2][8][4];
#pragma unroll
    for (int mi = 0; mi < 2; mi++)
#pragma unroll
        for (int ni = 0; ni < 8; ni++)
#pragma unroll
            for (int j = 0; j < 4; j++) acc[mi][ni][j] = 0.f;

    {
        float4 va[4]; uint4 vb[4];
        tf_issueA(A, lda, m0, 0, tid, va);
        tf_commitA(smem, tid, va);
        tf_issueB(W, K, n0, 0, tid, vb);
        tf_commitB(smem + TFTILE_A, tid, vb);
    }
    __syncthreads();

    int g = lid >> 2, t4 = lid & 3;
    int mbase = (wid & 3) * 32, nbase = (wid >> 2) * 64;
    int KT = K / 32;

    for (int kt = 0; kt < KT; kt++) {
        char* cur = smem + (kt & 1) * TFSTAGE;
        char* nxt = smem + ((kt + 1) & 1) * TFSTAGE;
        float4 va[4]; uint4 vb[4];
        bool more = (kt + 1 < KT);
        if (more) {
            tf_issueA(A, lda, m0, (kt + 1) * 32, tid, va);
            tf_issueB(W, K, n0, (kt + 1) * 32, tid, vb);
        }
        char* Ac = cur;
        char* Bc = cur + TFTILE_A;
#pragma unroll
        for (int ks = 0; ks < 4; ks++) {
            int kc = ks * 8;
            uint32_t a[2][4];
#pragma unroll
            for (int mi = 0; mi < 2; mi++) {
                int r = mbase + mi * 16 + g;
                a[mi][0] = *(uint32_t*)(Ac + r * TFROW_A + (kc + t4) * 4);
                a[mi][1] = *(uint32_t*)(Ac + (r + 8) * TFROW_A + (kc + t4) * 4);
                a[mi][2] = *(uint32_t*)(Ac + r * TFROW_A + (kc + t4 + 4) * 4);
                a[mi][3] = *(uint32_t*)(Ac + (r + 8) * TFROW_A + (kc + t4 + 4) * 4);
            }
            int bb = t4 * 32 + ks * 8;
#pragma unroll
            for (int ni = 0; ni < 8; ni++) {
                int rn = nbase + ni * 8 + g;
                uint2 pb = *(uint2*)(Bc + rn * TFROW_B + bb);
#pragma unroll
                for (int mi = 0; mi < 2; mi++)
                    MMA_TF32(acc[mi][ni], a[mi][0], a[mi][1], a[mi][2], a[mi][3], pb.x, pb.y);
            }
        }
        if (more) {
            tf_commitA(nxt, tid, va);
            tf_commitB(nxt + TFTILE_A, tid, vb);
        }
        __syncthreads();
    }

#pragma unroll
    for (int mi = 0; mi < 2; mi++)
#pragma unroll
        for (int ni = 0; ni < 8; ni++) {
            int gm = m0 + mbase + mi * 16 + g;
            int gn = n0 + nbase + ni * 8 + t4 * 2;
            const float* c = acc[mi][ni];
#pragma unroll
            for (int hrow = 0; hrow < 2; hrow++) {
                long long ci = (long long)(gm + hrow * 8) * ldc + gn;
#pragma unroll
                for (int j = 0; j < 2; j++) {
                    float v = c[hrow * 2 + j] * scale;
                    if (EPI == 1)      v += bias[gn + j];
                    else if (EPI == 2) v = 1.f / (1.f + expf(-(v + bias[gn + j])));
                    else if (EPI == 3) v += bias[gn + j] + Cm[ci + j];
                    Cm[ci + j] = v;
                }
            }
        }
}

// =====================================================================
//     attention scores: S = Q K^T / 8  (split-bf16, K=64, z = b*H+h)
// =====================================================================
__global__ void __launch_bounds__(256, 1) attn_sc_k(
    const float* __restrict__ qkv, const float* __restrict__ kf,
    float* __restrict__ sc)
{
    extern __shared__ char smem[];
    int z = blockIdx.z, b = z >> 4, h = z & 15;
    int m0 = blockIdx.y * 128, n0 = blockIdx.x * 128;
    const float* A  = qkv + (long long)b * C_ * 3072 + h * 64;
    const float* Bp = kf + (long long)b * PC_ * D_ + h * 64;
    int tid = threadIdx.x, wid = tid >> 5, lid = tid & 31;

#pragma unroll
    for (int kc = 0; kc < 2; kc++) {
        float4 va[4];
        issue_f32<0>(A, 3072, m0, kc * 32, tid, va);
        commit_f32<0>(smem + kc * 2 * TILE_B, smem + kc * 2 * TILE_B + TILE_B, tid, va);
        int r = tid >> 1, hh = tid & 1;
        int j = n0 + r;
        float4 vb[4];
        if (j < PC_) {
#pragma unroll
            for (int i = 0; i < 4; i++)
                vb[i] = *(const float4*)(Bp + (long long)j * D_ + kc * 32 + hh * 16 + i * 4);
        } else {
#pragma unroll
            for (int i = 0; i < 4; i++) vb[i] = make_float4(0.f, 0.f, 0.f, 0.f);
        }
        commit_f32<0>(smem + (4 + kc * 2) * TILE_B, smem + (4 + kc * 2) * TILE_B + TILE_B, tid, vb);
    }
    __syncthreads();

    int g = lid >> 2, t4 = lid & 3;
    int mbase = (wid & 3) * 32, nbase = (wid >> 2) * 64;
    float acc[2][8][4];
#pragma unroll
    for (int mi = 0; mi < 2; mi++)
#pragma unroll
        for (int ni = 0; ni < 8; ni++)
#pragma unroll
            for (int j = 0; j < 4; j++) acc[mi][ni][j] = 0.f;

#pragma unroll
    for (int kc = 0; kc < 2; kc++) {
        char* Ah = smem + kc * 2 * TILE_B;       char* Al = Ah + TILE_B;
        char* Bh = smem + (4 + kc * 2) * TILE_B; char* Bl = Bh + TILE_B;
#pragma unroll
        for (int k16 = 0; k16 < 2; k16++) {
            int kcc = k16 * 16;
            uint32_t ah[2][4], al[2][4];
#pragma unroll
            for (int mi = 0; mi < 2; mi++) {
                int r = mbase + mi * 16 + g;
                int c = kcc + t4 * 2;
                ah[mi][0] = *(uint32_t*)(Ah + r * 80 + c * 2);
                ah[mi][1] = *(uint32_t*)(Ah + (r + 8) * 80 + c * 2);
                ah[mi][2] = *(uint32_t*)(Ah + r * 80 + (c + 8) * 2);
                ah[mi][3] = *(uint32_t*)(Ah + (r + 8) * 80 + (c + 8) * 2);
                al[mi][0] = *(uint32_t*)(Al + r * 80 + c * 2);
                al[mi][1] = *(uint32_t*)(Al + (r + 8) * 80 + c * 2);
                al[mi][2] = *(uint32_t*)(Al + r * 80 + (c + 8) * 2);
                al[mi][3] = *(uint32_t*)(Al + (r + 8) * 80 + (c + 8) * 2);
            }
#pragma unroll
            for (int ni = 0; ni < 8; ni++) {
                int r = nbase + ni * 8 + g;
                int c = kcc + t4 * 2;
                uint32_t bh0 = *(uint32_t*)(Bh + r * 80 + c * 2);
                uint32_t bh1 = *(uint32_t*)(Bh + r * 80 + (c + 8) * 2);
                uint32_t bl0 = *(uint32_t*)(Bl + r * 80 + c * 2);
                uint32_t bl1 = *(uint32_t*)(Bl + r * 80 + (c + 8) * 2);
#pragma unroll
                for (int mi = 0; mi < 2; mi++) {
                    MMA_B16(acc[mi][ni], ah[mi][0], ah[mi][1], ah[mi][2], ah[mi][3], bh0, bh1);
                    MMA_B16(acc[mi][ni], ah[mi][0], ah[mi][1], ah[mi][2], ah[mi][3], bl0, bl1);
                    MMA_B16(acc[mi][ni], al[mi][0], al[mi][1], al[mi][2], al[mi][3], bh0, bh1);
                }
            }
        }
    }
#pragma unroll
    for (int mi = 0; mi < 2; mi++)
#pragma unroll
        for (int ni = 0; ni < 8; ni++) {
            int gm = m0 + mbase + mi * 16 + g;
            int gn = n0 + nbase + ni * 8 + t4 * 2;
            const float* c = acc[mi][ni];
#pragma unroll
            for (int hrow = 0; hrow < 2; hrow++) {
                long long ci = ((long long)z * C_ + gm + hrow * 8) * PCs + gn;
                sc[ci]     = c[hrow * 2 + 0] * 0.125f;
                sc[ci + 1] = c[hrow * 2 + 1] * 0.125f;
            }
        }
}

// =====================================================================
//     attention P@V: ao[s][h*64+d] = sum_j P[s][j] V[j][d]   (K=544)
// =====================================================================
__global__ void __launch_bounds__(256) attn_pv_k(
    const float* __restrict__ sc, const float* __restrict__ vf,
    float* __restrict__ ao)
{
    __shared__ char sP[2 * TILE_B];
    __shared__ char sV[2 * 5120];
    int z = blockIdx.y, b = z >> 4, h = z & 15;
    int m0 = blockIdx.x * 128;
    const float* P = sc + ((long long)z * C_ + m0) * PCs;
    const float* V = vf + (long long)b * PC_ * D_ + h * 64;
    int tid = threadIdx.x, wid = tid >> 5, lid = tid & 31;
    int g = lid >> 2, t4 = lid & 3;

    float acc[8][4];
#pragma unroll
    for (int ni = 0; ni < 8; ni++)
#pragma unroll
        for (int j = 0; j < 4; j++) acc[ni][j] = 0.f;

    for (int kt = 0; kt < 17; kt++) {
        int k0 = kt * 32;
        float4 vp[4];
        issue_f32<0>(P, PCs, 0, k0, tid, vp);
        int jj = tid >> 3, d0 = (tid & 7) * 8;
        int j = k0 + jj;
        float4 v0 = make_float4(0.f, 0.f, 0.f, 0.f), v1 = v0;
        if (j < PC_) {
            v0 = *(const float4*)(V + (long long)j * D_ + d0);
            v1 = *(const float4*)(V + (long long)j * D_ + d0 + 4);
        }
        __syncthreads();
        commit_f32<0>(sP, sP + TILE_B, tid, vp);
        {
            float xs[8] = {v0.x, v0.y, v0.z, v0.w, v1.x, v1.y, v1.z, v1.w};
#pragma unroll
            for (int e = 0; e < 8; e++) {
                int d = d0 + e;
                __nv_bfloat16 hh, ll;
                cvt2(xs[e], hh, ll);
                *(__nv_bfloat16*)(sV + d * 80 + jj * 2) = hh;
                *(__nv_bfloat16*)(sV + 5120 + d * 80 + jj * 2) = ll;
            }
        }
        __syncthreads();
#pragma unroll
        for (int k16 = 0; k16 < 2; k16++) {
            int c = k16 * 16 + t4 * 2;
            int r = wid * 16 + g;
            uint32_t ph[4], pl[4];
            ph[0] = *(uint32_t*)(sP + r * 80 + c * 2);
            ph[1] = *(uint32_t*)(sP + (r + 8) * 80 + c * 2);
            ph[2] = *(uint32_t*)(sP + r * 80 + (c + 8) * 2);
            ph[3] = *(uint32_t*)(sP + (r + 8) * 80 + (c + 8) * 2);
            pl[0] = *(uint32_t*)(sP + TILE_B + r * 80 + c * 2);
            pl[1] = *(uint32_t*)(sP + TILE_B + (r + 8) * 80 + c * 2);
            pl[2] = *(uint32_t*)(sP + TILE_B + r * 80 + (c + 8) * 2);
            pl[3] = *(uint32_t*)(sP + TILE_B + (r + 8) * 80 + (c + 8) * 2);
#pragma unroll
            for (int ni = 0; ni < 8; ni++) {
                int d = ni * 8 + g;
                uint32_t bh0 = *(uint32_t*)(sV + d * 80 + c * 2);
                uint32_t bh1 = *(uint32_t*)(sV + d * 80 + (c + 8) * 2);
                uint32_t bl0 = *(uint32_t*)(sV + 5120 + d * 80 + c * 2);
                uint32_t bl1 = *(uint32_t*)(sV + 5120 + d * 80 + (c + 8) * 2);
                MMA_B16(acc[ni], ph[0], ph[1], ph[2], ph[3], bh0, bh1);
                MMA_B16(acc[ni], ph[0], ph[1], ph[2], ph[3], bl0, bl1);
                MMA_B16(acc[ni], pl[0], pl[1], pl[2], pl[3], bh0, bh1);
            }
        }
    }
#pragma unroll
    for (int ni = 0; ni < 8; ni++) {
        int gm = m0 + wid * 16 + g;
        int gn = ni * 8 + t4 * 2;
        float* o = ao + ((long long)b * C_ + gm) * D_ + h * 64 + gn;
        o[0] = acc[ni][0]; o[1] = acc[ni][1];
        float* o2 = o + 8 * D_;
        o2[0] = acc[ni][2]; o2[1] = acc[ni][3];
    }
}

// ---------------- block reductions ----------------
__device__ __forceinline__ float blockReduceSum(float v) {
    __shared__ float sh[33];
    int lane = threadIdx.x & 31, w = threadIdx.x >> 5, nw = blockDim.x >> 5;
#pragma unroll
    for (int o = 16; o; o >>= 1) v += __shfl_xor_sync(0xffffffffu, v, o);
    __syncthreads();
    if (lane == 0) sh[w] = v;
    __syncthreads();
    if (w == 0) {
        float t = (lane < nw) ? sh[lane] : 0.f;
#pragma unroll
        for (int o = 16; o; o >>= 1) t += __shfl_xor_sync(0xffffffffu, t, o);
        if (lane == 0) sh[32] = t;
    }
    __syncthreads();
    return sh[32];
}

// ---------------- layernorm ----------------
__global__ void ln_kernel(const float* __restrict__ xin, int gather, int c0,
                          const float* __restrict__ add,
                          const float* __restrict__ gamma, const float* __restrict__ beta,
                          float* __restrict__ out)
{
    int t = blockIdx.x;
    const float* px;
    if (gather) {
        int b = t >> 9, s = t & 511;
        px = xin + ((size_t)b * S_ + c0 + s) * D_;
    } else {
        px = xin + (size_t)t * D_;
    }
    int i0 = threadIdx.x * 4;
    float4 v = *(const float4*)(px + i0);
    if (add) {
        float4 a = *(const float4*)(add + (size_t)t * D_ + i0);
        v.x += a.x; v.y += a.y; v.z += a.z; v.w += a.w;
    }
    float mean = blockReduceSum(v.x + v.y + v.z + v.w) * (1.f / D_);
    float dx = v.x - mean, dy = v.y - mean, dz = v.z - mean, dw = v.w - mean;
    float var = blockReduceSum(dx*dx + dy*dy + dz*dz + dw*dw) * (1.f / D_);
    float inv = rsqrtf(var + 1e-5f);
    float4 gv = *(const float4*)(gamma + i0);
    float4 bv = *(const float4*)(beta + i0);
    float4 o;
    o.x = dx * inv * gv.x + bv.x;
    o.y = dy * inv * gv.y + bv.y;
    o.z = dz * inv * gv.z + bv.z;
    o.w = dw * inv * gv.w + bv.w;
    *(float4*)(out + (size_t)t * D_ + i0) = o;
}

__global__ void rownorm_kernel(float* __restrict__ a, int ld, int off) {
    int t = blockIdx.x;
    float* p = a + (size_t)t * ld + off;
    int i0 = threadIdx.x * 4;
    float4 v = *(const float4*)(p + i0);
    float ss = blockReduceSum(v.x*v.x + v.y*v.y + v.z*v.z + v.w*v.w);
    float inv = rsqrtf(ss + 1e-6f);
    v.x *= inv; v.y *= inv; v.z *= inv; v.w *= inv;
    *(float4*)(p + i0) = v;
}

// warp-per-row softmax: block=256 handles 8 rows
__global__ void softmax_kernel(float* __restrict__ sc) {
    int row = blockIdx.x * 8 + (threadIdx.x >> 5);
    int lane = threadIdx.x & 31;
    int i = row & (C_ - 1);
    int valid = P_ + i + 1;
    float* r = sc + (size_t)row * PCs;
    float mx = -1e30f;
    for (int j = lane; j < valid; j += 32) mx = fmaxf(mx, r[j]);
#pragma unroll
    for (int o = 16; o; o >>= 1) mx = fmaxf(mx, __shfl_xor_sync(0xffffffffu, mx, o));
    float s = 0.f;
    for (int j = lane; j < valid; j += 32) { float e = expf(r[j] - mx); r[j] = e; s += e; }
#pragma unroll
    for (int o = 16; o; o >>= 1) s += __shfl_xor_sync(0xffffffffu, s, o);
    float inv = 1.f / s;
    for (int j = lane; j < PCs; j += 32) r[j] = (j < valid) ? r[j] * inv : 0.f;
}

__global__ void pack_kernel(const float* __restrict__ pk, const float* __restrict__ pv,
                            const float* __restrict__ qkv,
                            float* __restrict__ kf, float* __restrict__ vf)
{
    int bj = blockIdx.x;
    int b = bj / PC_, j = bj - b * PC_;
    size_t dst = (size_t)bj * D_ + threadIdx.x * 4;
    float4 kq, vq;
    if (j < P_) {
        kq = *(const float4*)(pk + (size_t)j * D_ + threadIdx.x * 4);
        vq = *(const float4*)(pv + (size_t)j * D_ + threadIdx.x * 4);
    } else {
        size_t row = ((size_t)b * C_ + (j - P_)) * 3072;
        kq = *(const float4*)(qkv + row + 1024 + threadIdx.x * 4);
        vq = *(const float4*)(qkv + row + 2048 + threadIdx.x * 4);
    }
    *(float4*)(kf + dst) = kq;
    *(float4*)(vf + dst) = vq;
}

__global__ void zero2_kernel(float4* a, float4* b, int n4) {
    int i = blockIdx.x * blockDim.x + threadIdx.x;
    float4 z = make_float4(0.f, 0.f, 0.f, 0.f);
    if (i < n4) { a[i] = z; b[i] = z; }
}
__global__ void update_kernel(float4* __restrict__ M, float4* __restrict__ St,
                              const float4* __restrict__ grad,
                              const float* lr, const float* mom, const float* fg, int n4) {
    float theta = 1.f / (1.f + expf(-lr[0]));
    float eta   = 1.f / (1.f + expf(-mom[0]));
    float alpha = 1.f / (1.f + expf(-fg[0]));
    int i = blockIdx.x * blockDim.x + threadIdx.x;
    if (i < n4) {
        float4 st = St[i], gr = grad[i], m = M[i];
        st.x = eta * st.x - theta * gr.x;
        st.y = eta * st.y - theta * gr.y;
        st.z = eta * st.z - theta * gr.z;
        st.w = eta * st.w - theta * gr.w;
        St[i] = st;
        m.x = (1.f - alpha) * m.x + st.x;
        m.y = (1.f - alpha) * m.y + st.y;
        m.z = (1.f - alpha) * m.z + st.z;
        m.w = (1.f - alpha) * m.w + st.w;
        M[i] = m;
    }
}
__global__ void combine_kernel(const float* __restrict__ x, const float4* __restrict__ gt,
                               const float4* __restrict__ ap, const float4* __restrict__ mem,
                               float* __restrict__ out, int c0) {
    int i = blockIdx.x * blockDim.x + threadIdx.x;
    int t = i >> 8, d = (i & 255) * 4;
    int b = t >> 9, s = t & 511;
    size_t xi = ((size_t)b * S_ + c0 + s) * D_ + d;
    float4 xv = *(const float4*)(x + xi);
    float4 g = gt[i], a = ap[i], m = mem[i];
    float4 o;
    o.x = xv.x + g.x * a.x + (1.f - g.x) * m.x;
    o.y = xv.y + g.y * a.y + (1.f - g.y) * m.y;
    o.z = xv.z + g.z * a.z + (1.f - g.z) * m.z;
    o.w = xv.w + g.w * a.w + (1.f - g.w) * m.w;
    *(float4*)(out + xi) = o;
}
__global__ void silu_kernel(float* __restrict__ ff) {
    int i = blockIdx.x * blockDim.x + threadIdx.x;   // NTOK*FF/4
    int t = i >> 10, d = (i & 1023) * 4;
    size_t o = (size_t)t * 8192 + d;
    float4 a = *(const float4*)(ff + o);
    float4 b = *(const float4*)(ff + o + 4096);
    a.x = a.x / (1.f + expf(-a.x)) * b.x;
    a.y = a.y / (1.f + expf(-a.y)) * b.y;
    a.z = a.z / (1.f + expf(-a.z)) * b.z;
    a.w = a.w / (1.f + expf(-a.w)) * b.w;
    *(float4*)(ff + o) = a;
}

// ---------------- host side ----------------
static float* symaddr(const void* s) {
    void* p = nullptr;
    cudaGetSymbolAddress(&p, s);
    return (float*)p;
}

template<int TRA, int TRB, int EPI>
static void mm(const float* A, const float* Bf, const float* bias, float* Cm,
               int M, int N, int K, long long lda, long long ldb, long long ldc,
               float scale, int Z, int zdiv,
               long long aO, long long aI, long long bO, long long bI,
               long long cO, long long cI)
{
    cudaFuncSetAttribute(mm_k<TRA, TRB, EPI>,
                         cudaFuncAttributeMaxDynamicSharedMemorySize, SMEM_MM);
    dim3 grid(N / 128, M / 128, Z);
    mm_k<TRA, TRB, EPI><<<grid, 256, SMEM_MM>>>(
        A, Bf, bias, Cm, M, N, K, lda, ldb, ldc, scale, zdiv,
        aO, aI, bO, bI, cO, cI);
}

template<int EPI>
static void mmtf(const float* A, const uint32_t* W, const float* bias, float* Cm,
                 int M, int N, int K, long long lda, long long ldc, float scale,
                 int Z, long long aO, long long cO)
{
    cudaFuncSetAttribute(mmtf_k<EPI>,
                         cudaFuncAttributeMaxDynamicSharedMemorySize, SMEM_TF);
    dim3 grid(N / 128, M / 128, Z);
    mmtf_k<EPI><<<grid, 256, SMEM_TF>>>(A, W, bias, Cm, M, N, K, lda, ldc,
                                        scale, aO, cO);
}

extern "C" void kernel_launch(void* const* d_in, const int* in_sizes, int n_in,
                              void* d_out, int out_size)
{
    const float* x     = (const float*)d_in[0];
    const float* g1    = (const float*)d_in[1];
    const float* b1    = (const float*)d_in[2];
    const float* g2    = (const float*)d_in[3];
    const float* b2p   = (const float*)d_in[4];
    const float* g3    = (const float*)d_in[5];
    const float* b3    = (const float*)d_in[6];
    const float* Wqm   = (const float*)d_in[7];
    const float* Wkm   = (const float*)d_in[8];
    const float* Wvm   = (const float*)d_in[9];
    const float* lr    = (const float*)d_in[10];
    const float* mom   = (const float*)d_in[11];
    const float* fg    = (const float*)d_in[12];
    const float* Wq    = (const float*)d_in[13];
    const float* bq    = (const float*)d_in[14];
    const float* Wk    = (const float*)d_in[15];
    const float* bk    = (const float*)d_in[16];
    const float* Wv    = (const float*)d_in[17];
    const float* bv    = (const float*)d_in[18];
    const float* Wo    = (const float*)d_in[19];
    const float* bo    = (const float*)d_in[20];
    const float* pk    = (const float*)d_in[21];
    const float* pv    = (const float*)d_in[22];
    const float* Wg    = (const float*)d_in[23];
    const float* bg    = (const float*)d_in[24];
    const float* Wgate = (const float*)d_in[25];
    const float* bgate = (const float*)d_in[26];
    const float* Wup   = (const float*)d_in[27];
    const float* bup   = (const float*)d_in[28];
    const float* Wdown = (const float*)d_in[29];
    const float* bdown = (const float*)d_in[30];
    float* out = (float*)d_out;

    float* pM   = symaddr(g_M);
    float* pSt  = symaddr(g_St);
    float* pGr  = symaddr(g_grad);
    float* ph1  = symaddr(g_h1);
    float* pmm3 = symaddr(g_mm3);
    float* pmp  = symaddr(g_mp);
    float* pmem = pmp;
    float* ppr  = pmp + (size_t)NTOK * D_;
    float* ph2  = symaddr(g_h2);
    float* pqkv = symaddr(g_qkv);
    float* pkf  = symaddr(g_kf);
    float* pvf  = symaddr(g_vf);
    float* psc  = symaddr(g_sc);
    float* pao  = symaddr(g_ao);
    float* pap  = symaddr(g_ap);
    float* pgt  = symaddr(g_gt);
    float* ph3  = symaddr(g_h3);
    float* pff  = symaddr(g_ff);
    float* pb3  = symaddr(g_bias3);
    float* pbff = symaddr(g_biasff);
    uint32_t* wt = (uint32_t*)symaddr(g_wt);

    const long long oWqm = 0, oWq = 3145728,
                    oWo = 6291456, oWg = 7340032,
                    oWgate = 8388608, oWdown = 16777216;

    dim3 blk(32, 8);
    wtf32_k<<<dim3(D_/32, D_/32), blk>>>(Wqm, wt + oWqm,           D_, D_);
    wtf32_k<<<dim3(D_/32, D_/32), blk>>>(Wkm, wt + oWqm + 1048576, D_, D_);
    wtf32_k<<<dim3(D_/32, D_/32), blk>>>(Wvm, wt + oWqm + 2097152, D_, D_);

    const int BDD = B_ * D_ * D_;
    zero2_kernel<<<(BDD/4 + 255) / 256, 256>>>((float4*)pM, (float4*)pSt, BDD/4);

    const long long CD  = (long long)C_ * D_;
    const long long DD  = (long long)D_ * D_;

    cudaFuncSetAttribute(attn_sc_k, cudaFuncAttributeMaxDynamicSharedMemorySize, SMEM_MM);

    for (int c = 0; c < NCH; c++) {
        int c0 = c * C_;

        ln_kernel<<<NTOK, 256>>>(x, 1, c0, nullptr, g1, b1, ph1);

        // merged neural-memory projections (tf32)
        mmtf<0>(ph1, wt + oWqm, nullptr, pmm3, NTOK, 3072, D_, D_, 3072, 1.f, 1, 0, 0);

        if (c == 0) {
            wtf32_k<<<dim3(D_/32, D_/32),  blk>>>(Wq,    wt + oWq,              D_, D_);
            wtf32_k<<<dim3(D_/32, D_/32),  blk>>>(Wk,    wt + oWq + 1048576,    D_, D_);
            wtf32_k<<<dim3(D_/32, D_/32),  blk>>>(Wv,    wt + oWq + 2097152,    D_, D_);
            wtf32_k<<<dim3(D_/32, D_/32),  blk>>>(Wo,    wt + oWo,              D_, D_);
            wtf32_k<<<dim3(D_/32, D_/32),  blk>>>(Wg,    wt + oWg,              D_, D_);
            wtf32_k<<<dim3(FF_/32, D_/32), blk>>>(Wgate, wt + oWgate,           D_, FF_);
            wtf32_k<<<dim3(FF_/32, D_/32), blk>>>(Wup,   wt + oWgate + 4194304, D_, FF_);
            wtf32_k<<<dim3(D_/32, FF_/32), blk>>>(Wdown, wt + oWdown,           FF_, D_);
            cat3_k<<<12, 256>>>(bq, bk, bv, pb3);
            cat2_k<<<32, 256>>>(bgate, bup, pbff);
        }

        rownorm_kernel<<<NTOK, 256>>>(pmm3, 3072, 1024);

        // mem/pred (bf16 split); pred half gets vm subtracted in epilogue (EPI=4)
        mm<0,0,4>(pmm3, pM, pmm3 + 2048, pmp, C_, D_, D_,
                  3072, D_, D_, 1.f, 8, 4,
                  1024, (long long)C_ * 3072, 0, DD,
                  (long long)NTOK * D_, CD);

        mm<1,1,0>(ppr, pmm3 + 1024, nullptr, pGr, D_, D_, C_,
                  D_, 3072, D_, 1.f / C_, B_, 1,
                  CD, 0, (long long)C_ * 3072, 0, DD, 0);

        update_kernel<<<(BDD/4 + 255) / 256, 256>>>((float4*)pM, (float4*)pSt,
                                                    (const float4*)pGr, lr, mom, fg, BDD/4);

        ln_kernel<<<NTOK, 256>>>(x, 1, c0, pmem, g2, b2p, ph2);

        // merged q,k,v (tf32)
        mmtf<1>(ph2, wt + oWq, pb3, pqkv, NTOK, 3072, D_, D_, 3072, 1.f, 1, 0, 0);

        pack_kernel<<<B_ * PC_, 256>>>(pk, pv, pqkv, pkf, pvf);

        attn_sc_k<<<dim3(5, 4, B_ * H_), 256, SMEM_MM>>>(pqkv, pkf, psc);
        softmax_kernel<<<B_ * H_ * C_ / 8, 256>>>(psc);
        attn_pv_k<<<dim3(4, B_ * H_), 256>>>(psc, pvf, pao);

        mmtf<1>(pao,  wt + oWo, bo, pap, NTOK, D_, D_, D_, D_, 1.f, 1, 0, 0);
        mmtf<2>(pmem, wt + oWg, bg, pgt, NTOK, D_, D_, D_, D_, 1.f, 1, 0, 0);

        combine_kernel<<<(NTOK * D_ / 4 + 255) / 256, 256>>>(x, (const float4*)pgt,
                                                             (const float4*)pap,
                                                             (const float4*)pmem, out, c0);

        ln_kernel<<<NTOK, 256>>>(out, 1, c0, nullptr, g3, b3, ph3);
        mmtf<1>(ph3, wt + oWgate, pbff, pff, NTOK, 8192, D_, D_, 8192, 1.f, 1, 0, 0);
        silu_kernel<<<(NTOK * FF_ / 4 + 255) / 256, 256>>>(pff);
        mmtf<3>(pff, wt + oWdown, bdown, out + (size_t)c0 * D_,
                C_, D_, FF_, 8192, D_, 1.f, B_,
                (long long)C_ * 8192, (long long)S_ * D_);
    }
}

// round 17
// speedup vs baseline: 1.2366x; 1.0197x over previous
#include <cuda_runtime.h>
#include <cuda_bf16.h>
#include <math.h>
#include <stdint.h>

// ---------------- problem constants ----------------
#define B_   4
#define S_   4096
#define D_   1024
#define H_   16
#define DH_  64
#define P_   16
#define C_   512
#define FF_  4096
#define NTOK 2048      /* B_*C_ tokens per chunk */
#define PC_  528       /* P_ + C_ */
#define PCs  640       /* padded score stride */
#define NCH  8         /* S_/C_ chunks */

// ---------------- device scratch (no allocation allowed) ----------------
__device__ float g_M   [(size_t)B_*D_*D_];      // TRANSPOSED: Mt[v][k] = M[k][v]
__device__ float g_St  [(size_t)B_*D_*D_];
__device__ uint32_t g_Mtf[(size_t)B_*D_*D_];    // Mt in tf32, k pair-permuted
__device__ float g_grad[(size_t)B_*D_*D_];
__device__ float g_h1  [(size_t)NTOK*D_];
__device__ float g_mm3 [(size_t)NTOK*3072];     // [qm|km|vm] ld=3072
__device__ float g_mp  [(size_t)2*NTOK*D_];     // [mem_ctx ; pred-vm] contiguous
__device__ float g_h2  [(size_t)NTOK*D_];
__device__ float g_qkv [(size_t)NTOK*3072];     // [qh|kh|vh] ld=3072
__device__ float g_kf  [(size_t)B_*PC_*D_];
__device__ float g_vf  [(size_t)B_*PC_*D_];
__device__ float g_sc  [(size_t)B_*H_*C_*PCs];
__device__ float g_ao  [(size_t)NTOK*D_];
__device__ float g_ap  [(size_t)NTOK*D_];
__device__ float g_gt  [(size_t)NTOK*D_];
__device__ float g_h3  [(size_t)NTOK*D_];
__device__ float g_ff  [(size_t)NTOK*8192];     // [gate|up] ld=8192
__device__ float g_bias3 [3072];
__device__ float g_bias2 [2048];                // [bo|bg]
__device__ float g_biasff[8192];
// pre-transposed weights [N,K] in tf32 (u32), k pair-permuted per 32-chunk
#define WTOT 20971520
__device__ uint32_t g_wt[WTOT];

__device__ __forceinline__ void cvt2(float x, __nv_bfloat16& h, __nv_bfloat16& l) {
    h = __float2bfloat16(x);
    l = __float2bfloat16(x - __bfloat162float(h));
}
__device__ __forceinline__ uint32_t f2tf(float x) {
    uint32_t r; asm("cvt.rna.tf32.f32 %0, %1;" : "=r"(r) : "f"(x)); return r;
}
// logical k -> pair-permuted storage col within its 32-chunk
__device__ __forceinline__ int kperm(int k) {
    return (k & ~31) + ((k & 3) << 3) + (((k >> 3) & 3) << 1) + ((k >> 2) & 1);
}

// =====================================================================
//   weight transpose+tf32:  src[K,N] fp32 -> dst[N,K] tf32, pair-permuted
// =====================================================================
__global__ void wtf32_k(const float* __restrict__ src, uint32_t* __restrict__ dst,
                        int K, int N)
{
    __shared__ float t[32][33];
    int nb = blockIdx.x * 32, kb = blockIdx.y * 32;
    int tx = threadIdx.x, ty = threadIdx.y;
#pragma unroll
    for (int i = 0; i < 32; i += 8)
        t[ty + i][tx] = src[(long long)(kb + ty + i) * N + nb + tx];
    __syncthreads();
    int ks = tx >> 3, rem = tx & 7;
    int s_local = (rem & 3) * 8 + ks * 2 + (rem >> 2);
#pragma unroll
    for (int i = 0; i < 32; i += 8) {
        long long o = (long long)(nb + ty + i) * K + kb + s_local;
        dst[o] = f2tf(t[tx][ty + i]);
    }
}

__global__ void cat3_k(const float* a, const float* b, const float* c, float* d) {
    int i = blockIdx.x * 256 + threadIdx.x;
    d[i] = (i < 1024) ? a[i] : (i < 2048) ? b[i - 1024] : c[i - 2048];
}
__global__ void cat2_k(const float* a, const float* b, float* d) {
    int i = blockIdx.x * 256 + threadIdx.x;
    d[i] = (i < 4096) ? a[i] : b[i - 4096];
}
__global__ void cat2b_k(const float* a, const float* b, float* d) {
    int i = blockIdx.x * 256 + threadIdx.x;
    d[i] = (i < 1024) ? a[i] : b[i - 1024];
}

// =====================================================================
//      bf16 split GEMM (grad GEMM): block 128x128x32, 8 warps
// =====================================================================
#define TILE_B 10240              /* 128 rows x 80 bytes */
#define SMEM_MM (8*TILE_B)        /* 81920 */

#define MMA_B16(c, a0, a1, a2, a3, b0, b1)                                     \
    asm volatile("mma.sync.aligned.m16n8k16.row.col.f32.bf16.bf16.f32 "        \
                 "{%0,%1,%2,%3}, {%4,%5,%6,%7}, {%8,%9}, {%0,%1,%2,%3};"       \
                 : "+f"(c[0]), "+f"(c[1]), "+f"(c[2]), "+f"(c[3])              \
                 : "r"(a0), "r"(a1), "r"(a2), "r"(a3), "r"(b0), "r"(b1))

#define MMA_TF32(c, a0, a1, a2, a3, b0, b1)                                    \
    asm volatile("mma.sync.aligned.m16n8k8.row.col.f32.tf32.tf32.f32 "         \
                 "{%0,%1,%2,%3}, {%4,%5,%6,%7}, {%8,%9}, {%0,%1,%2,%3};"       \
                 : "+f"(c[0]), "+f"(c[1]), "+f"(c[2]), "+f"(c[3])              \
                 : "r"(a0), "r"(a1), "r"(a2), "r"(a3), "r"(b0), "r"(b1))

// ---- fp32 loaders (bf16 hi/lo commit) ----
template<int TR>
__device__ __forceinline__ void issue_f32(const float* __restrict__ src, long long ld,
                                          int row0, int k0, int tid, float4 v[4]) {
    if (TR == 0) {
        int r = tid >> 1, h = tid & 1;
#pragma unroll
        for (int i = 0; i < 4; i++)
            v[i] = *(const float4*)(src + (long long)(row0 + r) * ld + k0 + h * 16 + i * 4);
    } else {
        int kk = tid >> 3, q = tid & 7;
#pragma unroll
        for (int i = 0; i < 4; i++)
            v[i] = *(const float4*)(src + (long long)(k0 + kk) * ld + row0 + (q + i * 8) * 4);
    }
}
template<int TR>
__device__ __forceinline__ void commit_f32(char* dhi, char* dlo, int tid, const float4 v[4]) {
    if (TR == 0) {
        int r = tid >> 1, h = tid & 1;
#pragma unroll
        for (int i = 0; i < 4; i++) {
            int c = h * 16 + i * 4;
            __nv_bfloat16 h0, h1, h2, h3, l0, l1, l2, l3;
            cvt2(v[i].x, h0, l0); cvt2(v[i].y, h1, l1);
            cvt2(v[i].z, h2, l2); cvt2(v[i].w, h3, l3);
            uint2 hp, lp;
            hp.x = (uint32_t)__bfloat16_as_ushort(h0) | ((uint32_t)__bfloat16_as_ushort(h1) << 16);
            hp.y = (uint32_t)__bfloat16_as_ushort(h2) | ((uint32_t)__bfloat16_as_ushort(h3) << 16);
            lp.x = (uint32_t)__bfloat16_as_ushort(l0) | ((uint32_t)__bfloat16_as_ushort(l1) << 16);
            lp.y = (uint32_t)__bfloat16_as_ushort(l2) | ((uint32_t)__bfloat16_as_ushort(l3) << 16);
            *(uint2*)(dhi + r * 80 + c * 2) = hp;
            *(uint2*)(dlo + r * 80 + c * 2) = lp;
        }
    } else {
        int kk = tid >> 3, q = tid & 7;
#pragma unroll
        for (int i = 0; i < 4; i++) {
            int m = (q + i * 8) * 4;
            float xs[4] = {v[i].x, v[i].y, v[i].z, v[i].w};
#pragma unroll
            for (int j = 0; j < 4; j++) {
                __nv_bfloat16 h, l;
                cvt2(xs[j], h, l);
                *(__nv_bfloat16*)(dhi + (m + j) * 80 + kk * 2) = h;
                *(__nv_bfloat16*)(dlo + (m + j) * 80 + kk * 2) = l;
            }
        }
    }
}

template<int TRA, int TRB, int EPI>
__global__ void __launch_bounds__(256, 1) mm_k(
    const float* __restrict__ A, const float* __restrict__ Bf,
    const float* __restrict__ bias, float* __restrict__ Cm,
    int M, int N, int K, long long lda, long long ldb, long long ldc, float scale,
    int zdiv,
    long long aO, long long aI, long long bO, long long bI, long long cO, long long cI)
{
    extern __shared__ char smem[];
    int z = blockIdx.z;
    int zq = z / zdiv, zr = z % zdiv;
    A  += zq * aO + zr * aI;
    Bf += zq * bO + zr * bI;
    Cm += zq * cO + zr * cI;

    int tid = threadIdx.x, wid = tid >> 5, lid = tid & 31;
    int m0 = blockIdx.y * 128, n0 = blockIdx.x * 128;

    float acc[2][8][4];
#pragma unroll
    for (int mi = 0; mi < 2; mi++)
#pragma unroll
        for (int ni = 0; ni < 8; ni++)
#pragma unroll
            for (int j = 0; j < 4; j++) acc[mi][ni][j] = 0.f;

    {
        float4 va[4], vb[4];
        issue_f32<TRA>(A, lda, m0, 0, tid, va);
        commit_f32<TRA>(smem, smem + TILE_B, tid, va);
        issue_f32<TRB>(Bf, ldb, n0, 0, tid, vb);
        commit_f32<TRB>(smem + 2 * TILE_B, smem + 3 * TILE_B, tid, vb);
    }
    __syncthreads();

    int g = lid >> 2, t4 = lid & 3;
    int mbase = (wid & 3) * 32, nbase = (wid >> 2) * 64;
    int KT = K / 32;

    for (int kt = 0; kt < KT; kt++) {
        char* cur = smem + (kt & 1) * 4 * TILE_B;
        char* nxt = smem + ((kt + 1) & 1) * 4 * TILE_B;
        float4 va[4], vb[4];
        bool more = (kt + 1 < KT);
        if (more) {
            issue_f32<TRA>(A, lda, m0, (kt + 1) * 32, tid, va);
            issue_f32<TRB>(Bf, ldb, n0, (kt + 1) * 32, tid, vb);
        }
        char* Ah = cur;              char* Al = cur + TILE_B;
        char* Bh = cur + 2 * TILE_B; char* Bl = cur + 3 * TILE_B;
#pragma unroll
        for (int k16 = 0; k16 < 2; k16++) {
            int kc = k16 * 16;
            uint32_t ah[2][4], al[2][4];
#pragma unroll
            for (int mi = 0; mi < 2; mi++) {
                int r = mbase + mi * 16 + g;
                int c = kc + t4 * 2;
                ah[mi][0] = *(uint32_t*)(Ah + r * 80 + c * 2);
                ah[mi][1] = *(uint32_t*)(Ah + (r + 8) * 80 + c * 2);
                ah[mi][2] = *(uint32_t*)(Ah + r * 80 + (c + 8) * 2);
                ah[mi][3] = *(uint32_t*)(Ah + (r + 8) * 80 + (c + 8) * 2);
                al[mi][0] = *(uint32_t*)(Al + r * 80 + c * 2);
                al[mi][1] = *(uint32_t*)(Al + (r + 8) * 80 + c * 2);
                al[mi][2] = *(uint32_t*)(Al + r * 80 + (c + 8) * 2);
                al[mi][3] = *(uint32_t*)(Al + (r + 8) * 80 + (c + 8) * 2);
            }
#pragma unroll
            for (int ni = 0; ni < 8; ni++) {
                int r = nbase + ni * 8 + g;
                int c = kc + t4 * 2;
                uint32_t bh0 = *(uint32_t*)(Bh + r * 80 + c * 2);
                uint32_t bh1 = *(uint32_t*)(Bh + r * 80 + (c + 8) * 2);
                uint32_t bl0 = *(uint32_t*)(Bl + r * 80 + c * 2);
                uint32_t bl1 = *(uint32_t*)(Bl + r * 80 + (c + 8) * 2);
#pragma unroll
                for (int mi = 0; mi < 2; mi++) {
                    MMA_B16(acc[mi][ni], ah[mi][0], ah[mi][1], ah[mi][2], ah[mi][3], bh0, bh1);
                    MMA_B16(acc[mi][ni], ah[mi][0], ah[mi][1], ah[mi][2], ah[mi][3], bl0, bl1);
                    MMA_B16(acc[mi][ni], al[mi][0], al[mi][1], al[mi][2], al[mi][3], bh0, bh1);
                }
            }
        }
        if (more) {
            commit_f32<TRA>(nxt, nxt + TILE_B, tid, va);
            commit_f32<TRB>(nxt + 2 * TILE_B, nxt + 3 * TILE_B, tid, vb);
        }
        __syncthreads();
    }

#pragma unroll
    for (int mi = 0; mi < 2; mi++)
#pragma unroll
        for (int ni = 0; ni < 8; ni++) {
            int gm = m0 + mbase + mi * 16 + g;
            int gn = n0 + nbase + ni * 8 + t4 * 2;
            const float* c = acc[mi][ni];
#pragma unroll
            for (int hrow = 0; hrow < 2; hrow++) {
                long long ci = (long long)(gm + hrow * 8) * ldc + gn;
#pragma unroll
                for (int j = 0; j < 2; j++) {
                    float v = c[hrow * 2 + j] * scale;
                    if (EPI == 1)      v += bias[gn + j];
                    else if (EPI == 2) v = 1.f / (1.f + expf(-(v + bias[gn + j])));
                    else if (EPI == 3) v += bias[gn + j] + Cm[ci + j];
                    Cm[ci + j] = v;
                }
            }
        }
}

// =====================================================================
//      TF32 single-pass GEMM: block 128x128x32
//      A: linear layout, stride 144.  B: pair-permuted tf32, stride 136.
//      EPI: 0 store, 1 +bias, 2 sigmoid(+bias), 3 accum(+bias),
//           4 pred-minus-vm (zq==1), 5 merged Wo|Wg (z-dep bias/sigmoid)
// =====================================================================
#define TFROW_A 144
#define TFROW_B 136
#define TFTILE_A (128*TFROW_A)
#define TFTILE_B (128*TFROW_B)
#define TFSTAGE  (TFTILE_A+TFTILE_B)
#define SMEM_TF  (2*TFSTAGE)

__device__ __forceinline__ void tf_issueA(const float* __restrict__ src, long long ld,
                                          int row0, int k0, int tid, float4 v[4]) {
    int r = tid >> 1, h = tid & 1;
#pragma unroll
    for (int i = 0; i < 4; i++)
        v[i] = *(const float4*)(src + (long long)(row0 + r) * ld + k0 + h * 16 + i * 4);
}
__device__ __forceinline__ void tf_commitA(char* d, int tid, const float4 v[4]) {
    int r = tid >> 1, h = tid & 1;
#pragma unroll
    for (int i = 0; i < 4; i++) {
        uint4 u;
        u.x = f2tf(v[i].x); u.y = f2tf(v[i].y); u.z = f2tf(v[i].z); u.w = f2tf(v[i].w);
        *(uint4*)(d + r * TFROW_A + (h * 16 + i * 4) * 4) = u;
    }
}
__device__ __forceinline__ void tf_issueB(const uint32_t* __restrict__ src, long long K,
                                          int n0, int k0, int tid, uint4 v[4]) {
    int r = tid >> 1, h = tid & 1;
#pragma unroll
    for (int i = 0; i < 4; i++)
        v[i] = *(const uint4*)(src + (long long)(n0 + r) * K + k0 + h * 16 + i * 4);
}
// 8B stores only (TFROW_B=136 not 16B-aligned for odd rows)
__device__ __forceinline__ void tf_commitB(char* d, int tid, const uint4 v[4]) {
    int r = tid >> 1, h = tid & 1;
    char* base = d + r * TFROW_B + h * 64;
#pragma unroll
    for (int i = 0; i < 4; i++) {
        *(uint2*)(base + i * 16)     = make_uint2(v[i].x, v[i].y);
        *(uint2*)(base + i * 16 + 8) = make_uint2(v[i].z, v[i].w);
    }
}

template<int EPI>
__global__ void __launch_bounds__(256, 1) mmtf_k(
    const float* __restrict__ A, const uint32_t* __restrict__ W,
    const float* __restrict__ bias, float* __restrict__ Cm,
    int M, int N, int K, long long lda, long long ldc, float scale,
    int zdiv,
    long long aO, long long aI, long long bO, long long bI,
    long long cO, long long cI)
{
    extern __shared__ char smem[];
    int z = blockIdx.z;
    int zq = z / zdiv, zr = z % zdiv;
    A  += zq * aO + zr * aI;
    W  += zq * bO + zr * bI;
    Cm += zq * cO + zr * cI;

    int tid = threadIdx.x, wid = tid >> 5, lid = tid & 31;
    int m0 = blockIdx.y * 128, n0 = blockIdx.x * 128;

    float acc[2][8][4];
#pragma unroll
    for (int mi = 0; mi < 2; mi++)
#pragma unroll
        for (int ni = 0; ni < 8; ni++)
#pragma unroll
            for (int j = 0; j < 4; j++) acc[mi][ni][j] = 0.f;

    {
        float4 va[4]; uint4 vb[4];
        tf_issueA(A, lda, m0, 0, tid, va);
        tf_commitA(smem, tid, va);
        tf_issueB(W, K, n0, 0, tid, vb);
        tf_commitB(smem + TFTILE_A, tid, vb);
    }
    __syncthreads();

    int g = lid >> 2, t4 = lid & 3;
    int mbase = (wid & 3) * 32, nbase = (wid >> 2) * 64;
    int KT = K / 32;

    for (int kt = 0; kt < KT; kt++) {
        char* cur = smem + (kt & 1) * TFSTAGE;
        char* nxt = smem + ((kt + 1) & 1) * TFSTAGE;
        float4 va[4]; uint4 vb[4];
        bool more = (kt + 1 < KT);
        if (more) {
            tf_issueA(A, lda, m0, (kt + 1) * 32, tid, va);
            tf_issueB(W, K, n0, (kt + 1) * 32, tid, vb);
        }
        char* Ac = cur;
        char* Bc = cur + TFTILE_A;
#pragma unroll
        for (int ks = 0; ks < 4; ks++) {
            int kc = ks * 8;
            uint32_t a[2][4];
#pragma unroll
            for (int mi = 0; mi < 2; mi++) {
                int r = mbase + mi * 16 + g;
                a[mi][0] = *(uint32_t*)(Ac + r * TFROW_A + (kc + t4) * 4);
                a[mi][1] = *(uint32_t*)(Ac + (r + 8) * TFROW_A + (kc + t4) * 4);
                a[mi][2] = *(uint32_t*)(Ac + r * TFROW_A + (kc + t4 + 4) * 4);
                a[mi][3] = *(uint32_t*)(Ac + (r + 8) * TFROW_A + (kc + t4 + 4) * 4);
            }
            int bb = t4 * 32 + ks * 8;
#pragma unroll
            for (int ni = 0; ni < 8; ni++) {
                int rn = nbase + ni * 8 + g;
                uint2 pb = *(uint2*)(Bc + rn * TFROW_B + bb);
#pragma unroll
                for (int mi = 0; mi < 2; mi++)
                    MMA_TF32(acc[mi][ni], a[mi][0], a[mi][1], a[mi][2], a[mi][3], pb.x, pb.y);
            }
        }
        if (more) {
            tf_commitA(nxt, tid, va);
            tf_commitB(nxt + TFTILE_A, tid, vb);
        }
        __syncthreads();
    }

#pragma unroll
    for (int mi = 0; mi < 2; mi++)
#pragma unroll
        for (int ni = 0; ni < 8; ni++) {
            int gm = m0 + mbase + mi * 16 + g;
            int gn = n0 + nbase + ni * 8 + t4 * 2;
            const float* c = acc[mi][ni];
#pragma unroll
            for (int hrow = 0; hrow < 2; hrow++) {
                long long ci = (long long)(gm + hrow * 8) * ldc + gn;
#pragma unroll
                for (int j = 0; j < 2; j++) {
                    float v = c[hrow * 2 + j] * scale;
                    if (EPI == 1)      v += bias[gn + j];
                    else if (EPI == 2) v = 1.f / (1.f + expf(-(v + bias[gn + j])));
                    else if (EPI == 3) v += bias[gn + j] + Cm[ci + j];
                    else if (EPI == 4) {
                        if (zq == 1)
                            v -= bias[((long long)zr * C_ + gm + hrow * 8) * 3072 + gn + j];
                    } else if (EPI == 5) {
                        v += bias[(long long)z * 1024 + gn + j];
                        if (z == 1) v = 1.f / (1.f + expf(-v));
                    }
                    Cm[ci + j] = v;
                }
            }
        }
}

// =====================================================================
//     attention scores: S = Q K^T / 8  (split-bf16, K=64, z = b*H+h)
// =====================================================================
__global__ void __launch_bounds__(256, 1) attn_sc_k(
    const float* __restrict__ qkv, const float* __restrict__ kf,
    float* __restrict__ sc)
{
    extern __shared__ char smem[];
    int z = blockIdx.z, b = z >> 4, h = z & 15;
    int m0 = blockIdx.y * 128, n0 = blockIdx.x * 128;
    const float* A  = qkv + (long long)b * C_ * 3072 + h * 64;
    const float* Bp = kf + (long long)b * PC_ * D_ + h * 64;
    int tid = threadIdx.x, wid = tid >> 5, lid = tid & 31;

#pragma unroll
    for (int kc = 0; kc < 2; kc++) {
        float4 va[4];
        issue_f32<0>(A, 3072, m0, kc * 32, tid, va);
        commit_f32<0>(smem + kc * 2 * TILE_B, smem + kc * 2 * TILE_B + TILE_B, tid, va);
        int r = tid >> 1, hh = tid & 1;
        int j = n0 + r;
        float4 vb[4];
        if (j < PC_) {
#pragma unroll
            for (int i = 0; i < 4; i++)
                vb[i] = *(const float4*)(Bp + (long long)j * D_ + kc * 32 + hh * 16 + i * 4);
        } else {
#pragma unroll
            for (int i = 0; i < 4; i++) vb[i] = make_float4(0.f, 0.f, 0.f, 0.f);
        }
        commit_f32<0>(smem + (4 + kc * 2) * TILE_B, smem + (4 + kc * 2) * TILE_B + TILE_B, tid, vb);
    }
    __syncthreads();

    int g = lid >> 2, t4 = lid & 3;
    int mbase = (wid & 3) * 32, nbase = (wid >> 2) * 64;
    float acc[2][8][4];
#pragma unroll
    for (int mi = 0; mi < 2; mi++)
#pragma unroll
        for (int ni = 0; ni < 8; ni++)
#pragma unroll
            for (int j = 0; j < 4; j++) acc[mi][ni][j] = 0.f;

#pragma unroll
    for (int kc = 0; kc < 2; kc++) {
        char* Ah = smem + kc * 2 * TILE_B;       char* Al = Ah + TILE_B;
        char* Bh = smem + (4 + kc * 2) * TILE_B; char* Bl = Bh + TILE_B;
#pragma unroll
        for (int k16 = 0; k16 < 2; k16++) {
            int kcc = k16 * 16;
            uint32_t ah[2][4], al[2][4];
#pragma unroll
            for (int mi = 0; mi < 2; mi++) {
                int r = mbase + mi * 16 + g;
                int c = kcc + t4 * 2;
                ah[mi][0] = *(uint32_t*)(Ah + r * 80 + c * 2);
                ah[mi][1] = *(uint32_t*)(Ah + (r + 8) * 80 + c * 2);
                ah[mi][2] = *(uint32_t*)(Ah + r * 80 + (c + 8) * 2);
                ah[mi][3] = *(uint32_t*)(Ah + (r + 8) * 80 + (c + 8) * 2);
                al[mi][0] = *(uint32_t*)(Al + r * 80 + c * 2);
                al[mi][1] = *(uint32_t*)(Al + (r + 8) * 80 + c * 2);
                al[mi][2] = *(uint32_t*)(Al + r * 80 + (c + 8) * 2);
                al[mi][3] = *(uint32_t*)(Al + (r + 8) * 80 + (c + 8) * 2);
            }
#pragma unroll
            for (int ni = 0; ni < 8; ni++) {
                int r = nbase + ni * 8 + g;
                int c = kcc + t4 * 2;
                uint32_t bh0 = *(uint32_t*)(Bh + r * 80 + c * 2);
                uint32_t bh1 = *(uint32_t*)(Bh + r * 80 + (c + 8) * 2);
                uint32_t bl0 = *(uint32_t*)(Bl + r * 80 + c * 2);
                uint32_t bl1 = *(uint32_t*)(Bl + r * 80 + (c + 8) * 2);
#pragma unroll
                for (int mi = 0; mi < 2; mi++) {
                    MMA_B16(acc[mi][ni], ah[mi][0], ah[mi][1], ah[mi][2], ah[mi][3], bh0, bh1);
                    MMA_B16(acc[mi][ni], ah[mi][0], ah[mi][1], ah[mi][2], ah[mi][3], bl0, bl1);
                    MMA_B16(acc[mi][ni], al[mi][0], al[mi][1], al[mi][2], al[mi][3], bh0, bh1);
                }
            }
        }
    }
#pragma unroll
    for (int mi = 0; mi < 2; mi++)
#pragma unroll
        for (int ni = 0; ni < 8; ni++) {
            int gm = m0 + mbase + mi * 16 + g;
            int gn = n0 + nbase + ni * 8 + t4 * 2;
            const float* c = acc[mi][ni];
#pragma unroll
            for (int hrow = 0; hrow < 2; hrow++) {
                long long ci = ((long long)z * C_ + gm + hrow * 8) * PCs + gn;
                sc[ci]     = c[hrow * 2 + 0] * 0.125f;
                sc[ci + 1] = c[hrow * 2 + 1] * 0.125f;
            }
        }
}

// =====================================================================
//     attention P@V: ao[s][h*64+d] = sum_j P[s][j] V[j][d]   (K=544)
// =====================================================================
__global__ void __launch_bounds__(256) attn_pv_k(
    const float* __restrict__ sc, const float* __restrict__ vf,
    float* __restrict__ ao)
{
    __shared__ char sP[2 * TILE_B];
    __shared__ char sV[2 * 5120];
    int z = blockIdx.y, b = z >> 4, h = z & 15;
    int m0 = blockIdx.x * 128;
    const float* P = sc + ((long long)z * C_ + m0) * PCs;
    const float* V = vf + (long long)b * PC_ * D_ + h * 64;
    int tid = threadIdx.x, wid = tid >> 5, lid = tid & 31;
    int g = lid >> 2, t4 = lid & 3;

    float acc[8][4];
#pragma unroll
    for (int ni = 0; ni < 8; ni++)
#pragma unroll
        for (int j = 0; j < 4; j++) acc[ni][j] = 0.f;

    for (int kt = 0; kt < 17; kt++) {
        int k0 = kt * 32;
        float4 vp[4];
        issue_f32<0>(P, PCs, 0, k0, tid, vp);
        int jj = tid >> 3, d0 = (tid & 7) * 8;
        int j = k0 + jj;
        float4 v0 = make_float4(0.f, 0.f, 0.f, 0.f), v1 = v0;
        if (j < PC_) {
            v0 = *(const float4*)(V + (long long)j * D_ + d0);
            v1 = *(const float4*)(V + (long long)j * D_ + d0 + 4);
        }
        __syncthreads();
        commit_f32<0>(sP, sP + TILE_B, tid, vp);
        {
            float xs[8] = {v0.x, v0.y, v0.z, v0.w, v1.x, v1.y, v1.z, v1.w};
#pragma unroll
            for (int e = 0; e < 8; e++) {
                int d = d0 + e;
                __nv_bfloat16 hh, ll;
                cvt2(xs[e], hh, ll);
                *(__nv_bfloat16*)(sV + d * 80 + jj * 2) = hh;
                *(__nv_bfloat16*)(sV + 5120 + d * 80 + jj * 2) = ll;
            }
        }
        __syncthreads();
#pragma unroll
        for (int k16 = 0; k16 < 2; k16++) {
            int c = k16 * 16 + t4 * 2;
            int r = wid * 16 + g;
            uint32_t ph[4], pl[4];
            ph[0] = *(uint32_t*)(sP + r * 80 + c * 2);
            ph[1] = *(uint32_t*)(sP + (r + 8) * 80 + c * 2);
            ph[2] = *(uint32_t*)(sP + r * 80 + (c + 8) * 2);
            ph[3] = *(uint32_t*)(sP + (r + 8) * 80 + (c + 8) * 2);
            pl[0] = *(uint32_t*)(sP + TILE_B + r * 80 + c * 2);
            pl[1] = *(uint32_t*)(sP + TILE_B + (r + 8) * 80 + c * 2);
            pl[2] = *(uint32_t*)(sP + TILE_B + r * 80 + (c + 8) * 2);
            pl[3] = *(uint32_t*)(sP + TILE_B + (r + 8) * 80 + (c + 8) * 2);
#pragma unroll
            for (int ni = 0; ni < 8; ni++) {
                int d = ni * 8 + g;
                uint32_t bh0 = *(uint32_t*)(sV + d * 80 + c * 2);
                uint32_t bh1 = *(uint32_t*)(sV + d * 80 + (c + 8) * 2);
                uint32_t bl0 = *(uint32_t*)(sV + 5120 + d * 80 + c * 2);
                uint32_t bl1 = *(uint32_t*)(sV + 5120 + d * 80 + (c + 8) * 2);
                MMA_B16(acc[ni], ph[0], ph[1], ph[2], ph[3], bh0, bh1);
                MMA_B16(acc[ni], ph[0], ph[1], ph[2], ph[3], bl0, bl1);
                MMA_B16(acc[ni], pl[0], pl[1], pl[2], pl[3], bh0, bh1);
            }
        }
    }
#pragma unroll
    for (int ni = 0; ni < 8; ni++) {
        int gm = m0 + wid * 16 + g;
        int gn = ni * 8 + t4 * 2;
        float* o = ao + ((long long)b * C_ + gm) * D_ + h * 64 + gn;
        o[0] = acc[ni][0]; o[1] = acc[ni][1];
        float* o2 = o + 8 * D_;
        o2[0] = acc[ni][2]; o2[1] = acc[ni][3];
    }
}

// ---------------- block reductions ----------------
__device__ __forceinline__ float blockReduceSum(float v) {
    __shared__ float sh[33];
    int lane = threadIdx.x & 31, w = threadIdx.x >> 5, nw = blockDim.x >> 5;
#pragma unroll
    for (int o = 16; o; o >>= 1) v += __shfl_xor_sync(0xffffffffu, v, o);
    __syncthreads();
    if (lane == 0) sh[w] = v;
    __syncthreads();
    if (w == 0) {
        float t = (lane < nw) ? sh[lane] : 0.f;
#pragma unroll
        for (int o = 16; o; o >>= 1) t += __shfl_xor_sync(0xffffffffu, t, o);
        if (lane == 0) sh[32] = t;
    }
    __syncthreads();
    return sh[32];
}

// ---------------- layernorm ----------------
__global__ void ln_kernel(const float* __restrict__ xin, int gather, int c0,
                          const float* __restrict__ add,
                          const float* __restrict__ gamma, const float* __restrict__ beta,
                          float* __restrict__ out)
{
    int t = blockIdx.x;
    const float* px;
    if (gather) {
        int b = t >> 9, s = t & 511;
        px = xin + ((size_t)b * S_ + c0 + s) * D_;
    } else {
        px = xin + (size_t)t * D_;
    }
    int i0 = threadIdx.x * 4;
    float4 v = *(const float4*)(px + i0);
    if (add) {
        float4 a = *(const float4*)(add + (size_t)t * D_ + i0);
        v.x += a.x; v.y += a.y; v.z += a.z; v.w += a.w;
    }
    float mean = blockReduceSum(v.x + v.y + v.z + v.w) * (1.f / D_);
    float dx = v.x - mean, dy = v.y - mean, dz = v.z - mean, dw = v.w - mean;
    float var = blockReduceSum(dx*dx + dy*dy + dz*dz + dw*dw) * (1.f / D_);
    float inv = rsqrtf(var + 1e-5f);
    float4 gv = *(const float4*)(gamma + i0);
    float4 bv = *(const float4*)(beta + i0);
    float4 o;
    o.x = dx * inv * gv.x + bv.x;
    o.y = dy * inv * gv.y + bv.y;
    o.z = dz * inv * gv.z + bv.z;
    o.w = dw * inv * gv.w + bv.w;
    *(float4*)(out + (size_t)t * D_ + i0) = o;
}

__global__ void rownorm_kernel(float* __restrict__ a, int ld, int off) {
    int t = blockIdx.x;
    float* p = a + (size_t)t * ld + off;
    int i0 = threadIdx.x * 4;
    float4 v = *(const float4*)(p + i0);
    float ss = blockReduceSum(v.x*v.x + v.y*v.y + v.z*v.z + v.w*v.w);
    float inv = rsqrtf(ss + 1e-6f);
    v.x *= inv; v.y *= inv; v.z *= inv; v.w *= inv;
    *(float4*)(p + i0) = v;
}

// warp-per-row softmax: block=256 handles 8 rows
__global__ void softmax_kernel(float* __restrict__ sc) {
    int row = blockIdx.x * 8 + (threadIdx.x >> 5);
    int lane = threadIdx.x & 31;
    int i = row & (C_ - 1);
    int valid = P_ + i + 1;
    float* r = sc + (size_t)row * PCs;
    float mx = -1e30f;
    for (int j = lane; j < valid; j += 32) mx = fmaxf(mx, r[j]);
#pragma unroll
    for (int o = 16; o; o >>= 1) mx = fmaxf(mx, __shfl_xor_sync(0xffffffffu, mx, o));
    float s = 0.f;
    for (int j = lane; j < valid; j += 32) { float e = expf(r[j] - mx); r[j] = e; s += e; }
#pragma unroll
    for (int o = 16; o; o >>= 1) s += __shfl_xor_sync(0xffffffffu, s, o);
    float inv = 1.f / s;
    for (int j = lane; j < PCs; j += 32) r[j] = (j < valid) ? r[j] * inv : 0.f;
}

__global__ void pack_kernel(const float* __restrict__ pk, const float* __restrict__ pv,
                            const float* __restrict__ qkv,
                            float* __restrict__ kf, float* __restrict__ vf)
{
    int bj = blockIdx.x;
    int b = bj / PC_, j = bj - b * PC_;
    size_t dst = (size_t)bj * D_ + threadIdx.x * 4;
    float4 kq, vq;
    if (j < P_) {
        kq = *(const float4*)(pk + (size_t)j * D_ + threadIdx.x * 4);
        vq = *(const float4*)(pv + (size_t)j * D_ + threadIdx.x * 4);
    } else {
        size_t row = ((size_t)b * C_ + (j - P_)) * 3072;
        kq = *(const float4*)(qkv + row + 1024 + threadIdx.x * 4);
        vq = *(const float4*)(qkv + row + 2048 + threadIdx.x * 4);
    }
    *(float4*)(kf + dst) = kq;
    *(float4*)(vf + dst) = vq;
}

__global__ void zero3_kernel(float4* a, float4* b, uint4* c, int n4) {
    int i = blockIdx.x * blockDim.x + threadIdx.x;
    if (i < n4) {
        a[i] = make_float4(0.f, 0.f, 0.f, 0.f);
        b[i] = make_float4(0.f, 0.f, 0.f, 0.f);
        c[i] = make_uint4(0u, 0u, 0u, 0u);
    }
}
// momentum update + dual-format M write (fp32 + tf32 pair-permuted)
__global__ void update_kernel(float4* __restrict__ M, float4* __restrict__ St,
                              const float4* __restrict__ grad,
                              uint32_t* __restrict__ Mtf,
                              const float* lr, const float* mom, const float* fg, int n4) {
    float theta = 1.f / (1.f + expf(-lr[0]));
    float eta   = 1.f / (1.f + expf(-mom[0]));
    float alpha = 1.f / (1.f + expf(-fg[0]));
    int i = blockIdx.x * blockDim.x + threadIdx.x;
    if (i < n4) {
        float4 st = St[i], gr = grad[i], m = M[i];
        st.x = eta * st.x - theta * gr.x;
        st.y = eta * st.y - theta * gr.y;
        st.z = eta * st.z - theta * gr.z;
        st.w = eta * st.w - theta * gr.w;
        St[i] = st;
        m.x = (1.f - alpha) * m.x + st.x;
        m.y = (1.f - alpha) * m.y + st.y;
        m.z = (1.f - alpha) * m.z + st.z;
        m.w = (1.f - alpha) * m.w + st.w;
        M[i] = m;
        // tf32 pair-permuted copy for the mem/pred GEMM B operand
        int e0 = i * 4;
        float ms[4] = {m.x, m.y, m.z, m.w};
#pragma unroll
        for (int j = 0; j < 4; j++) {
            int e = e0 + j;
            int r = e >> 10;            // row (b*D + v)
            int k = e & 1023;
            Mtf[((long long)r << 10) + kperm(k)] = f2tf(ms[j]);
        }
    }
}
__global__ void combine_kernel(const float* __restrict__ x, const float4* __restrict__ gt,
                               const float4* __restrict__ ap, const float4* __restrict__ mem,
                               float* __restrict__ out, int c0) {
    int i = blockIdx.x * blockDim.x + threadIdx.x;
    int t = i >> 8, d = (i & 255) * 4;
    int b = t >> 9, s = t & 511;
    size_t xi = ((size_t)b * S_ + c0 + s) * D_ + d;
    float4 xv = *(const float4*)(x + xi);
    float4 g = gt[i], a = ap[i], m = mem[i];
    float4 o;
    o.x = xv.x + g.x * a.x + (1.f - g.x) * m.x;
    o.y = xv.y + g.y * a.y + (1.f - g.y) * m.y;
    o.z = xv.z + g.z * a.z + (1.f - g.z) * m.z;
    o.w = xv.w + g.w * a.w + (1.f - g.w) * m.w;
    *(float4*)(out + xi) = o;
}
__global__ void silu_kernel(float* __restrict__ ff) {
    int i = blockIdx.x * blockDim.x + threadIdx.x;   // NTOK*FF/4
    int t = i >> 10, d = (i & 1023) * 4;
    size_t o = (size_t)t * 8192 + d;
    float4 a = *(const float4*)(ff + o);
    float4 b = *(const float4*)(ff + o + 4096);
    a.x = a.x / (1.f + expf(-a.x)) * b.x;
    a.y = a.y / (1.f + expf(-a.y)) * b.y;
    a.z = a.z / (1.f + expf(-a.z)) * b.z;
    a.w = a.w / (1.f + expf(-a.w)) * b.w;
    *(float4*)(ff + o) = a;
}

// ---------------- host side ----------------
static float* symaddr(const void* s) {
    void* p = nullptr;
    cudaGetSymbolAddress(&p, s);
    return (float*)p;
}

template<int TRA, int TRB, int EPI>
static void mm(const float* A, const float* Bf, const float* bias, float* Cm,
               int M, int N, int K, long long lda, long long ldb, long long ldc,
               float scale, int Z, int zdiv,
               long long aO, long long aI, long long bO, long long bI,
               long long cO, long long cI)
{
    cudaFuncSetAttribute(mm_k<TRA, TRB, EPI>,
                         cudaFuncAttributeMaxDynamicSharedMemorySize, SMEM_MM);
    dim3 grid(N / 128, M / 128, Z);
    mm_k<TRA, TRB, EPI><<<grid, 256, SMEM_MM>>>(
        A, Bf, bias, Cm, M, N, K, lda, ldb, ldc, scale, zdiv,
        aO, aI, bO, bI, cO, cI);
}

template<int EPI>
static void mmtf(const float* A, const uint32_t* W, const float* bias, float* Cm,
                 int M, int N, int K, long long lda, long long ldc, float scale,
                 int Z, int zdiv,
                 long long aO, long long aI, long long bO, long long bI,
                 long long cO, long long cI)
{
    cudaFuncSetAttribute(mmtf_k<EPI>,
                         cudaFuncAttributeMaxDynamicSharedMemorySize, SMEM_TF);
    dim3 grid(N / 128, M / 128, Z);
    mmtf_k<EPI><<<grid, 256, SMEM_TF>>>(A, W, bias, Cm, M, N, K, lda, ldc,
                                        scale, zdiv, aO, aI, bO, bI, cO, cI);
}

extern "C" void kernel_launch(void* const* d_in, const int* in_sizes, int n_in,
                              void* d_out, int out_size)
{
    const float* x     = (const float*)d_in[0];
    const float* g1    = (const float*)d_in[1];
    const float* b1    = (const float*)d_in[2];
    const float* g2    = (const float*)d_in[3];
    const float* b2p   = (const float*)d_in[4];
    const float* g3    = (const float*)d_in[5];
    const float* b3    = (const float*)d_in[6];
    const float* Wqm   = (const float*)d_in[7];
    const float* Wkm   = (const float*)d_in[8];
    const float* Wvm   = (const float*)d_in[9];
    const float* lr    = (const float*)d_in[10];
    const float* mom   = (const float*)d_in[11];
    const float* fg    = (const float*)d_in[12];
    const float* Wq    = (const float*)d_in[13];
    const float* bq    = (const float*)d_in[14];
    const float* Wk    = (const float*)d_in[15];
    const float* bk    = (const float*)d_in[16];
    const float* Wv    = (const float*)d_in[17];
    const float* bv    = (const float*)d_in[18];
    const float* Wo    = (const float*)d_in[19];
    const float* bo    = (const float*)d_in[20];
    const float* pk    = (const float*)d_in[21];
    const float* pv    = (const float*)d_in[22];
    const float* Wg    = (const float*)d_in[23];
    const float* bg    = (const float*)d_in[24];
    const float* Wgate = (const float*)d_in[25];
    const float* bgate = (const float*)d_in[26];
    const float* Wup   = (const float*)d_in[27];
    const float* bup   = (const float*)d_in[28];
    const float* Wdown = (const float*)d_in[29];
    const float* bdown = (const float*)d_in[30];
    float* out = (float*)d_out;

    float* pM   = symaddr(g_M);
    float* pSt  = symaddr(g_St);
    uint32_t* pMtf = (uint32_t*)symaddr(g_Mtf);
    float* pGr  = symaddr(g_grad);
    float* ph1  = symaddr(g_h1);
    float* pmm3 = symaddr(g_mm3);
    float* pmp  = symaddr(g_mp);
    float* pmem = pmp;
    float* ppr  = pmp + (size_t)NTOK * D_;
    float* ph2  = symaddr(g_h2);
    float* pqkv = symaddr(g_qkv);
    float* pkf  = symaddr(g_kf);
    float* pvf  = symaddr(g_vf);
    float* psc  = symaddr(g_sc);
    float* pao  = symaddr(g_ao);
    float* pap  = symaddr(g_ap);
    float* pgt  = symaddr(g_gt);
    float* ph3  = symaddr(g_h3);
    float* pff  = symaddr(g_ff);
    float* pb3  = symaddr(g_bias3);
    float* pb2  = symaddr(g_bias2);
    float* pbff = symaddr(g_biasff);
    uint32_t* wt = (uint32_t*)symaddr(g_wt);

    const long long oWqm = 0, oWq = 3145728,
                    oWo = 6291456, oWg = 7340032,
                    oWgate = 8388608, oWdown = 16777216;

    dim3 blk(32, 8);
    wtf32_k<<<dim3(D_/32, D_/32), blk>>>(Wqm, wt + oWqm,           D_, D_);
    wtf32_k<<<dim3(D_/32, D_/32), blk>>>(Wkm, wt + oWqm + 1048576, D_, D_);
    wtf32_k<<<dim3(D_/32, D_/32), blk>>>(Wvm, wt + oWqm + 2097152, D_, D_);

    const int BDD = B_ * D_ * D_;
    zero3_kernel<<<(BDD/4 + 255) / 256, 256>>>((float4*)pM, (float4*)pSt,
                                               (uint4*)pMtf, BDD/4);

    const long long CD  = (long long)C_ * D_;
    const long long DD  = (long long)D_ * D_;

    cudaFuncSetAttribute(attn_sc_k, cudaFuncAttributeMaxDynamicSharedMemorySize, SMEM_MM);

    for (int c = 0; c < NCH; c++) {
        int c0 = c * C_;

        ln_kernel<<<NTOK, 256>>>(x, 1, c0, nullptr, g1, b1, ph1);

        // merged neural-memory projections (tf32)
        mmtf<0>(ph1, wt + oWqm, nullptr, pmm3, NTOK, 3072, D_, D_, 3072, 1.f,
                1, 1, 0,0, 0,0, 0,0);

        if (c == 0) {
            wtf32_k<<<dim3(D_/32, D_/32),  blk>>>(Wq,    wt + oWq,              D_, D_);
            wtf32_k<<<dim3(D_/32, D_/32),  blk>>>(Wk,    wt + oWq + 1048576,    D_, D_);
            wtf32_k<<<dim3(D_/32, D_/32),  blk>>>(Wv,    wt + oWq + 2097152,    D_, D_);
            wtf32_k<<<dim3(D_/32, D_/32),  blk>>>(Wo,    wt + oWo,              D_, D_);
            wtf32_k<<<dim3(D_/32, D_/32),  blk>>>(Wg,    wt + oWg,              D_, D_);
            wtf32_k<<<dim3(FF_/32, D_/32), blk>>>(Wgate, wt + oWgate,           D_, FF_);
            wtf32_k<<<dim3(FF_/32, D_/32), blk>>>(Wup,   wt + oWgate + 4194304, D_, FF_);
            wtf32_k<<<dim3(D_/32, FF_/32), blk>>>(Wdown, wt + oWdown,           FF_, D_);
            cat3_k<<<12, 256>>>(bq, bk, bv, pb3);
            cat2b_k<<<8, 256>>>(bo, bg, pb2);
            cat2_k<<<32, 256>>>(bgate, bup, pbff);
        }

        rownorm_kernel<<<NTOK, 256>>>(pmm3, 3072, 1024);

        // mem/pred (tf32 single-pass, B = Mtf); pred half minus vm (EPI=4)
        // z = which*4 + b: zq=which (0=qm/mem, 1=km/pred), zr=b
        mmtf<4>(pmm3, pMtf, pmm3 + 2048, pmp, C_, D_, D_, 3072, D_, 1.f,
                8, 4,
                /*aO(which)*/1024, /*aI(b)*/(long long)C_ * 3072,
                /*bO*/0, /*bI*/DD,
                /*cO*/(long long)NTOK * D_, /*cI*/CD);

        // gradT = diff^T km / C  (bf16 split, transpose loads)
        mm<1,1,0>(ppr, pmm3 + 1024, nullptr, pGr, D_, D_, C_,
                  D_, 3072, D_, 1.f / C_, B_, 1,
                  CD, 0, (long long)C_ * 3072, 0, DD, 0);

        update_kernel<<<(BDD/4 + 255) / 256, 256>>>((float4*)pM, (float4*)pSt,
                                                    (const float4*)pGr, pMtf,
                                                    lr, mom, fg, BDD/4);

        ln_kernel<<<NTOK, 256>>>(x, 1, c0, pmem, g2, b2p, ph2);

        // merged q,k,v (tf32)
        mmtf<1>(ph2, wt + oWq, pb3, pqkv, NTOK, 3072, D_, D_, 3072, 1.f,
                1, 1, 0,0, 0,0, 0,0);

        pack_kernel<<<B_ * PC_, 256>>>(pk, pv, pqkv, pkf, pvf);

        attn_sc_k<<<dim3(5, 4, B_ * H_), 256, SMEM_MM>>>(pqkv, pkf, psc);
        softmax_kernel<<<B_ * H_ * C_ / 8, 256>>>(psc);
        attn_pv_k<<<dim3(4, B_ * H_), 256>>>(psc, pvf, pao);

        // merged Wo|Wg projection (z=0: ao->ap +bo ; z=1: mem->gt sigmoid(+bg))
        mmtf<5>(pao, wt + oWo, pb2, pap, NTOK, D_, D_, D_, D_, 1.f,
                2, 1,
                (long long)(pmem - pao), 0,
                DD, 0,
                (long long)(pgt - pap), 0);

        combine_kernel<<<(NTOK * D_ / 4 + 255) / 256, 256>>>(x, (const float4*)pgt,
                                                             (const float4*)pap,
                                                             (const float4*)pmem, out, c0);

        ln_kernel<<<NTOK, 256>>>(out, 1, c0, nullptr, g3, b3, ph3);
        mmtf<1>(ph3, wt + oWgate, pbff, pff, NTOK, 8192, D_, D_, 8192, 1.f,
                1, 1, 0,0, 0,0, 0,0);
        silu_kernel<<<(NTOK * FF_ / 4 + 255) / 256, 256>>>(pff);
        mmtf<3>(pff, wt + oWdown, bdown, out + (size_t)c0 * D_,
                C_, D_, FF_, 8192, D_, 1.f,
                B_, 1,
                (long long)C_ * 8192, 0, 0, 0, (long long)S_ * D_, 0);
    }
}